// round 6
// baseline (speedup 1.0000x reference)
#include <cuda_runtime.h>

// Problem constants
#define CB 2
#define CS 2048
#define CD 1024
#define CH 16
#define CHD 64
#define CM (CB*CS)   // 4096 tokens

// Scratch (allocation-free rule: __device__ globals)
__device__ float g_q[(size_t)CM * CD];        // 16 MB
__device__ float g_kvsum[(size_t)CM * 128];   // 2 MB  (cols 0..63 = k_sum, 64..127 = v_sum)
__device__ float g_attnout[(size_t)CM * CD];  // 16 MB
__device__ float g_Wkv[128 * CD];             // head-summed K/V weights
__device__ float g_bkv[128];

// ---------------------------------------------------------------------------
// Kernel 1: reduce Wqkv over heads -> Wk_sum (rows 0..63), Wv_sum (rows 64..127)
// ---------------------------------------------------------------------------
__global__ __launch_bounds__(256) void prep_k(const float* __restrict__ Wqkv,
                                              const float* __restrict__ bqkv)
{
    int idx = blockIdx.x * 256 + threadIdx.x;
    if (idx < 128 * 1024) {
        int r = idx >> 10;          // 0..127
        int c = idx & 1023;
        int rr = r & 63;
        int base = (r < 64 ? 1024 : 2048) + rr;
        float sum = 0.f;
        #pragma unroll
        for (int h = 0; h < 16; h++)
            sum += Wqkv[(size_t)(base + h * 64) * CD + c];
        g_Wkv[(size_t)r * CD + c] = sum;
    }
    if (idx < 128) {
        int rr = idx & 63;
        int base = (idx < 64 ? 1024 : 2048) + rr;
        float s = 0.f;
        #pragma unroll
        for (int h = 0; h < 16; h++)
            s += bqkv[base + h * 64];
        g_bkv[idx] = s;
    }
}

// ---------------------------------------------------------------------------
// SGEMM: C[m,n] = bias[n] + sum_k A[m,k] * B[n,k]   (both K-contiguous, "NT")
// BM=BN=128, BK=16, 256 threads, 8x8 per thread.
// MODE 0: A=x, N=1152 (cols <1024 from Wqkv -> g_q; cols >=1024 from g_Wkv -> g_kvsum)
// MODE 1: A=g_attnout, B=Wout, C=d_out
// ---------------------------------------------------------------------------
template<int MODE>
__global__ __launch_bounds__(256) void sgemm_k(const float* __restrict__ A,
                                               const float* __restrict__ Bw,
                                               const float* __restrict__ bias,
                                               float* __restrict__ Cout)
{
    const int K = CD;
    const int n0 = blockIdx.x * 128;
    const int m0 = blockIdx.y * 128;

    const float* Ap = (MODE == 0) ? A : g_attnout;
    const float* Bp;
    const float* bp;
    if (MODE == 0 && n0 >= CD) { Bp = g_Wkv; bp = g_bkv; }
    else                       { Bp = Bw + (size_t)n0 * K; bp = bias + n0; }

    __shared__ float As[16][132];
    __shared__ float Bs[16][132];

    const int tid = threadIdx.x;
    const int tx = tid & 15;
    const int ty = tid >> 4;

    float acc[8][8];
    #pragma unroll
    for (int i = 0; i < 8; i++)
        #pragma unroll
        for (int j = 0; j < 8; j++) acc[i][j] = 0.f;

    const float* Abase = Ap + (size_t)m0 * K;

    for (int k0 = 0; k0 < K; k0 += 16) {
        #pragma unroll
        for (int ii = 0; ii < 2; ii++) {
            int f = tid + ii * 256;          // 0..511
            int row = f >> 2;                // 0..127
            int c4 = (f & 3) << 2;           // 0,4,8,12
            float4 av = *(const float4*)(Abase + (size_t)row * K + k0 + c4);
            As[c4 + 0][row] = av.x; As[c4 + 1][row] = av.y;
            As[c4 + 2][row] = av.z; As[c4 + 3][row] = av.w;
            float4 bv = *(const float4*)(Bp + (size_t)row * K + k0 + c4);
            Bs[c4 + 0][row] = bv.x; Bs[c4 + 1][row] = bv.y;
            Bs[c4 + 2][row] = bv.z; Bs[c4 + 3][row] = bv.w;
        }
        __syncthreads();
        #pragma unroll
        for (int kk = 0; kk < 16; kk++) {
            float4 a0 = *(const float4*)&As[kk][ty * 8];
            float4 a1 = *(const float4*)&As[kk][ty * 8 + 4];
            float4 b0 = *(const float4*)&Bs[kk][tx * 8];
            float4 b1 = *(const float4*)&Bs[kk][tx * 8 + 4];
            float a[8] = {a0.x, a0.y, a0.z, a0.w, a1.x, a1.y, a1.z, a1.w};
            float b[8] = {b0.x, b0.y, b0.z, b0.w, b1.x, b1.y, b1.z, b1.w};
            #pragma unroll
            for (int i = 0; i < 8; i++)
                #pragma unroll
                for (int j = 0; j < 8; j++)
                    acc[i][j] += a[i] * b[j];
        }
        __syncthreads();
    }

    #pragma unroll
    for (int i = 0; i < 8; i++) {
        int m = m0 + ty * 8 + i;
        #pragma unroll
        for (int j = 0; j < 8; j += 4) {
            int nl = tx * 8 + j;
            float4 v;
            v.x = acc[i][j + 0] + bp[nl + 0];
            v.y = acc[i][j + 1] + bp[nl + 1];
            v.z = acc[i][j + 2] + bp[nl + 2];
            v.w = acc[i][j + 3] + bp[nl + 3];
            if (MODE == 0) {
                if (n0 < CD)
                    *(float4*)&g_q[(size_t)m * CD + n0 + nl] = v;
                else
                    *(float4*)&g_kvsum[(size_t)m * 128 + nl] = v;
            } else {
                *(float4*)&Cout[(size_t)m * CD + n0 + nl] = v;
            }
        }
    }
}

// ---------------------------------------------------------------------------
// Kernel 3: flash attention. Block = (b, s). 256 threads = 16 heads x 16 t-lanes.
// Thread (h,i): q row in regs, processes t = t0 + {0,16,32,48} + i per 64-key tile.
// Online softmax with finite -1e30 mask sentinel; combine over i via shfl.
// ---------------------------------------------------------------------------
__global__ __launch_bounds__(256) void attn_k()
{
    const int s = blockIdx.x;
    const int b = blockIdx.y;
    const int tid = threadIdx.x;
    const int h = tid >> 4;      // warp = 2 heads x 16 t-lanes
    const int i = tid & 15;

    __shared__ float ks[64][68]; // stride 68: float4-aligned rows, low conflicts
    __shared__ float vs[64][68];

    float qreg[CHD];
    {
        const float* qrow = g_q + ((size_t)(b * CS + s)) * CD + h * CHD;
        #pragma unroll
        for (int k = 0; k < CHD; k += 4) {
            float4 t4 = *(const float4*)(qrow + k);
            qreg[k] = t4.x; qreg[k + 1] = t4.y; qreg[k + 2] = t4.z; qreg[k + 3] = t4.w;
        }
    }

    float o[CHD];
    #pragma unroll
    for (int k = 0; k < CHD; k++) o[k] = 0.f;
    float m = -1e30f, l = 0.f;
    const float scale = 0.125f;  // 1/sqrt(64)

    const int row = tid >> 2;        // 0..63   (loading role)
    const int qq  = (tid & 3) << 4;  // 0,16,32,48

    for (int t0 = 0; t0 <= s; t0 += 64) {
        __syncthreads();
        {
            int t = t0 + row;
            if (t <= s) {
                const float* src = g_kvsum + ((size_t)(b * CS + t)) * 128 + qq;
                #pragma unroll
                for (int e = 0; e < 16; e += 4) {
                    float4 k4 = *(const float4*)(src + e);
                    float4 v4 = *(const float4*)(src + 64 + e);
                    ks[row][qq + e] = k4.x; ks[row][qq + e + 1] = k4.y;
                    ks[row][qq + e + 2] = k4.z; ks[row][qq + e + 3] = k4.w;
                    vs[row][qq + e] = v4.x; vs[row][qq + e + 1] = v4.y;
                    vs[row][qq + e + 2] = v4.z; vs[row][qq + e + 3] = v4.w;
                }
            } else {
                #pragma unroll
                for (int e = 0; e < 16; e++) { ks[row][qq + e] = 0.f; vs[row][qq + e] = 0.f; }
            }
        }
        __syncthreads();

        float sc[4];
        #pragma unroll
        for (int j = 0; j < 4; j++) {
            int tl = j * 16 + i;
            if (t0 + tl <= s) {
                float a0 = 0.f, a1 = 0.f, a2 = 0.f, a3 = 0.f;
                #pragma unroll
                for (int k = 0; k < CHD; k += 4) {
                    float4 k4 = *(const float4*)&ks[tl][k];
                    a0 += qreg[k] * k4.x;
                    a1 += qreg[k + 1] * k4.y;
                    a2 += qreg[k + 2] * k4.z;
                    a3 += qreg[k + 3] * k4.w;
                }
                sc[j] = ((a0 + a1) + (a2 + a3)) * scale;
            } else {
                sc[j] = -1e30f;   // finite sentinel: masked slots give p that is
                                  // exactly wiped by corr=exp(-1e30-cm)=0 later,
                                  // and vs rows beyond s are zeroed -> o unaffected
            }
        }
        float cm = fmaxf(fmaxf(sc[0], sc[1]), fmaxf(sc[2], sc[3]));
        if (cm > m) {
            float corr = __expf(m - cm);
            l *= corr;
            #pragma unroll
            for (int k = 0; k < CHD; k++) o[k] *= corr;
            m = cm;
        }
        float p0 = __expf(sc[0] - m);
        float p1 = __expf(sc[1] - m);
        float p2 = __expf(sc[2] - m);
        float p3 = __expf(sc[3] - m);
        l += (p0 + p1) + (p2 + p3);
        #pragma unroll
        for (int k = 0; k < CHD; k += 4) {
            float4 v0 = *(const float4*)&vs[i][k];
            float4 v1 = *(const float4*)&vs[16 + i][k];
            float4 v2 = *(const float4*)&vs[32 + i][k];
            float4 v3 = *(const float4*)&vs[48 + i][k];
            o[k]     += p0 * v0.x + p1 * v1.x + p2 * v2.x + p3 * v3.x;
            o[k + 1] += p0 * v0.y + p1 * v1.y + p2 * v2.y + p3 * v3.y;
            o[k + 2] += p0 * v0.z + p1 * v1.z + p2 * v2.z + p3 * v3.z;
            o[k + 3] += p0 * v0.w + p1 * v1.w + p2 * v2.w + p3 * v3.w;
        }
    }

    // Combine the 16 t-lane partials per head (lanes i=0..15 within half-warps).
    float mg = m;
    #pragma unroll
    for (int d = 8; d; d >>= 1)
        mg = fmaxf(mg, __shfl_xor_sync(0xffffffffu, mg, d, 16));
    float cf = __expf(m - mg);
    float lw = l * cf;
    #pragma unroll
    for (int d = 8; d; d >>= 1)
        lw += __shfl_xor_sync(0xffffffffu, lw, d, 16);
    #pragma unroll
    for (int k = 0; k < CHD; k++) o[k] *= cf;
    #pragma unroll
    for (int d = 8; d; d >>= 1) {
        #pragma unroll
        for (int k = 0; k < CHD; k++)
            o[k] += __shfl_xor_sync(0xffffffffu, o[k], d, 16);
    }

    if (i == 0) {
        float inv = 1.0f / lw;
        float* dst = g_attnout + ((size_t)(b * CS + s)) * CD + h * CHD;
        #pragma unroll
        for (int k = 0; k < CHD; k += 4) {
            float4 w;
            w.x = o[k] * inv; w.y = o[k + 1] * inv;
            w.z = o[k + 2] * inv; w.w = o[k + 3] * inv;
            *(float4*)(dst + k) = w;
        }
    }
}

// ---------------------------------------------------------------------------
extern "C" void kernel_launch(void* const* d_in, const int* in_sizes, int n_in,
                              void* d_out, int out_size)
{
    const float* x    = (const float*)d_in[0];
    const float* Wqkv = (const float*)d_in[1];
    const float* bqkv = (const float*)d_in[2];
    const float* Wout = (const float*)d_in[3];
    const float* bout = (const float*)d_in[4];
    float* out = (float*)d_out;

    // 1) head-sum the K/V weights+biases (linearity of the head reduction)
    prep_k<<<512, 256>>>(Wqkv, bqkv);
    // 2) fused q + kv_sum GEMM: N = 1024 (q) + 128 (k_sum|v_sum)
    sgemm_k<0><<<dim3(9, 32), 256>>>(x, Wqkv, bqkv, nullptr);
    // 3) causal flash attention over shared-key heads
    attn_k<<<dim3(CS, CB), 256>>>();
    // 4) output projection
    sgemm_k<1><<<dim3(8, 32), 256>>>(nullptr, Wout, bout, out);
}

// round 7
// speedup vs baseline: 1.0019x; 1.0019x over previous
#include <cuda_runtime.h>

// Problem constants
#define CB 2
#define CS 2048
#define CD 1024
#define CH 16
#define CHD 64
#define CM (CB*CS)   // 4096 tokens

// Scratch (allocation-free rule: __device__ globals)
__device__ float g_q[(size_t)CM * CD];        // 16 MB
__device__ float g_kvsum[(size_t)CM * 128];   // 2 MB  (cols 0..63 = k_sum, 64..127 = v_sum)
__device__ float g_attnout[(size_t)CM * CD];  // 16 MB
__device__ float g_Wkv[128 * CD];             // head-summed K/V weights
__device__ float g_bkv[128];

// ---------------------------------------------------------------------------
// Kernel 1: reduce Wqkv over heads -> Wk_sum (rows 0..63), Wv_sum (rows 64..127)
// ---------------------------------------------------------------------------
__global__ __launch_bounds__(256) void prep_k(const float* __restrict__ Wqkv,
                                              const float* __restrict__ bqkv)
{
    int idx = blockIdx.x * 256 + threadIdx.x;
    if (idx < 128 * 1024) {
        int r = idx >> 10;          // 0..127
        int c = idx & 1023;
        int rr = r & 63;
        int base = (r < 64 ? 1024 : 2048) + rr;
        float sum = 0.f;
        #pragma unroll
        for (int h = 0; h < 16; h++)
            sum += Wqkv[(size_t)(base + h * 64) * CD + c];
        g_Wkv[(size_t)r * CD + c] = sum;
    }
    if (idx < 128) {
        int rr = idx & 63;
        int base = (idx < 64 ? 1024 : 2048) + rr;
        float s = 0.f;
        #pragma unroll
        for (int h = 0; h < 16; h++)
            s += bqkv[base + h * 64];
        g_bkv[idx] = s;
    }
}

// ---------------------------------------------------------------------------
// SGEMM: C[m,n] = bias[n] + sum_k A[m,k] * B[n,k]   (both K-contiguous, "NT")
// BM=BN=128, BK=16, 256 threads, 8x8 per thread.
// MODE 0: A=x, N=1152 (cols <1024 from Wqkv -> g_q; cols >=1024 from g_Wkv -> g_kvsum)
// MODE 1: A=g_attnout, B=Wout, C=d_out
// ---------------------------------------------------------------------------
template<int MODE>
__global__ __launch_bounds__(256) void sgemm_k(const float* __restrict__ A,
                                               const float* __restrict__ Bw,
                                               const float* __restrict__ bias,
                                               float* __restrict__ Cout)
{
    const int K = CD;
    const int n0 = blockIdx.x * 128;
    const int m0 = blockIdx.y * 128;

    const float* Ap = (MODE == 0) ? A : g_attnout;
    const float* Bp;
    const float* bp;
    if (MODE == 0 && n0 >= CD) { Bp = g_Wkv; bp = g_bkv; }
    else                       { Bp = Bw + (size_t)n0 * K; bp = bias + n0; }

    __shared__ float As[16][132];
    __shared__ float Bs[16][132];

    const int tid = threadIdx.x;
    const int tx = tid & 15;
    const int ty = tid >> 4;

    float acc[8][8];
    #pragma unroll
    for (int i = 0; i < 8; i++)
        #pragma unroll
        for (int j = 0; j < 8; j++) acc[i][j] = 0.f;

    const float* Abase = Ap + (size_t)m0 * K;

    for (int k0 = 0; k0 < K; k0 += 16) {
        #pragma unroll
        for (int ii = 0; ii < 2; ii++) {
            int f = tid + ii * 256;          // 0..511
            int row = f >> 2;                // 0..127
            int c4 = (f & 3) << 2;           // 0,4,8,12
            float4 av = *(const float4*)(Abase + (size_t)row * K + k0 + c4);
            As[c4 + 0][row] = av.x; As[c4 + 1][row] = av.y;
            As[c4 + 2][row] = av.z; As[c4 + 3][row] = av.w;
            float4 bv = *(const float4*)(Bp + (size_t)row * K + k0 + c4);
            Bs[c4 + 0][row] = bv.x; Bs[c4 + 1][row] = bv.y;
            Bs[c4 + 2][row] = bv.z; Bs[c4 + 3][row] = bv.w;
        }
        __syncthreads();
        #pragma unroll
        for (int kk = 0; kk < 16; kk++) {
            float4 a0 = *(const float4*)&As[kk][ty * 8];
            float4 a1 = *(const float4*)&As[kk][ty * 8 + 4];
            float4 b0 = *(const float4*)&Bs[kk][tx * 8];
            float4 b1 = *(const float4*)&Bs[kk][tx * 8 + 4];
            float a[8] = {a0.x, a0.y, a0.z, a0.w, a1.x, a1.y, a1.z, a1.w};
            float b[8] = {b0.x, b0.y, b0.z, b0.w, b1.x, b1.y, b1.z, b1.w};
            #pragma unroll
            for (int i = 0; i < 8; i++)
                #pragma unroll
                for (int j = 0; j < 8; j++)
                    acc[i][j] += a[i] * b[j];
        }
        __syncthreads();
    }

    #pragma unroll
    for (int i = 0; i < 8; i++) {
        int m = m0 + ty * 8 + i;
        #pragma unroll
        for (int j = 0; j < 8; j += 4) {
            int nl = tx * 8 + j;
            float4 v;
            v.x = acc[i][j + 0] + bp[nl + 0];
            v.y = acc[i][j + 1] + bp[nl + 1];
            v.z = acc[i][j + 2] + bp[nl + 2];
            v.w = acc[i][j + 3] + bp[nl + 3];
            if (MODE == 0) {
                if (n0 < CD)
                    *(float4*)&g_q[(size_t)m * CD + n0 + nl] = v;
                else
                    *(float4*)&g_kvsum[(size_t)m * 128 + nl] = v;
            } else {
                *(float4*)&Cout[(size_t)m * CD + n0 + nl] = v;
            }
        }
    }
}

// ---------------------------------------------------------------------------
// Kernel 3: flash attention. Block = (b, s). 256 threads = 16 heads x 16 t-lanes.
// Thread (h,i): q row in regs, processes t = t0 + {0,16,32,48} + i per 64-key tile.
// Online softmax with finite -1e30 mask sentinel; combine over i via shfl.
// ---------------------------------------------------------------------------
__global__ __launch_bounds__(256) void attn_k()
{
    const int s = blockIdx.x;
    const int b = blockIdx.y;
    const int tid = threadIdx.x;
    const int h = tid >> 4;      // warp = 2 heads x 16 t-lanes
    const int i = tid & 15;

    __shared__ float ks[64][68]; // stride 68: float4-aligned rows, low conflicts
    __shared__ float vs[64][68];

    float qreg[CHD];
    {
        const float* qrow = g_q + ((size_t)(b * CS + s)) * CD + h * CHD;
        #pragma unroll
        for (int k = 0; k < CHD; k += 4) {
            float4 t4 = *(const float4*)(qrow + k);
            qreg[k] = t4.x; qreg[k + 1] = t4.y; qreg[k + 2] = t4.z; qreg[k + 3] = t4.w;
        }
    }

    float o[CHD];
    #pragma unroll
    for (int k = 0; k < CHD; k++) o[k] = 0.f;
    float m = -1e30f, l = 0.f;
    const float scale = 0.125f;  // 1/sqrt(64)

    const int row = tid >> 2;        // 0..63   (loading role)
    const int qq  = (tid & 3) << 4;  // 0,16,32,48

    for (int t0 = 0; t0 <= s; t0 += 64) {
        __syncthreads();
        {
            int t = t0 + row;
            if (t <= s) {
                const float* src = g_kvsum + ((size_t)(b * CS + t)) * 128 + qq;
                #pragma unroll
                for (int e = 0; e < 16; e += 4) {
                    float4 k4 = *(const float4*)(src + e);
                    float4 v4 = *(const float4*)(src + 64 + e);
                    ks[row][qq + e] = k4.x; ks[row][qq + e + 1] = k4.y;
                    ks[row][qq + e + 2] = k4.z; ks[row][qq + e + 3] = k4.w;
                    vs[row][qq + e] = v4.x; vs[row][qq + e + 1] = v4.y;
                    vs[row][qq + e + 2] = v4.z; vs[row][qq + e + 3] = v4.w;
                }
            } else {
                #pragma unroll
                for (int e = 0; e < 16; e++) { ks[row][qq + e] = 0.f; vs[row][qq + e] = 0.f; }
            }
        }
        __syncthreads();

        float sc[4];
        #pragma unroll
        for (int j = 0; j < 4; j++) {
            int tl = j * 16 + i;
            if (t0 + tl <= s) {
                float a0 = 0.f, a1 = 0.f, a2 = 0.f, a3 = 0.f;
                #pragma unroll
                for (int k = 0; k < CHD; k += 4) {
                    float4 k4 = *(const float4*)&ks[tl][k];
                    a0 += qreg[k] * k4.x;
                    a1 += qreg[k + 1] * k4.y;
                    a2 += qreg[k + 2] * k4.z;
                    a3 += qreg[k + 3] * k4.w;
                }
                sc[j] = ((a0 + a1) + (a2 + a3)) * scale;
            } else {
                sc[j] = -1e30f;   // finite sentinel: masked slots give p that is
                                  // exactly wiped by corr=exp(-1e30-cm)=0 later,
                                  // and vs rows beyond s are zeroed -> o unaffected
            }
        }
        float cm = fmaxf(fmaxf(sc[0], sc[1]), fmaxf(sc[2], sc[3]));
        if (cm > m) {
            float corr = __expf(m - cm);
            l *= corr;
            #pragma unroll
            for (int k = 0; k < CHD; k++) o[k] *= corr;
            m = cm;
        }
        float p0 = __expf(sc[0] - m);
        float p1 = __expf(sc[1] - m);
        float p2 = __expf(sc[2] - m);
        float p3 = __expf(sc[3] - m);
        l += (p0 + p1) + (p2 + p3);
        #pragma unroll
        for (int k = 0; k < CHD; k += 4) {
            float4 v0 = *(const float4*)&vs[i][k];
            float4 v1 = *(const float4*)&vs[16 + i][k];
            float4 v2 = *(const float4*)&vs[32 + i][k];
            float4 v3 = *(const float4*)&vs[48 + i][k];
            o[k]     += p0 * v0.x + p1 * v1.x + p2 * v2.x + p3 * v3.x;
            o[k + 1] += p0 * v0.y + p1 * v1.y + p2 * v2.y + p3 * v3.y;
            o[k + 2] += p0 * v0.z + p1 * v1.z + p2 * v2.z + p3 * v3.z;
            o[k + 3] += p0 * v0.w + p1 * v1.w + p2 * v2.w + p3 * v3.w;
        }
    }

    // Combine the 16 t-lane partials per head (lanes i=0..15 within half-warps).
    float mg = m;
    #pragma unroll
    for (int d = 8; d; d >>= 1)
        mg = fmaxf(mg, __shfl_xor_sync(0xffffffffu, mg, d, 16));
    float cf = __expf(m - mg);
    float lw = l * cf;
    #pragma unroll
    for (int d = 8; d; d >>= 1)
        lw += __shfl_xor_sync(0xffffffffu, lw, d, 16);
    #pragma unroll
    for (int k = 0; k < CHD; k++) o[k] *= cf;
    #pragma unroll
    for (int d = 8; d; d >>= 1) {
        #pragma unroll
        for (int k = 0; k < CHD; k++)
            o[k] += __shfl_xor_sync(0xffffffffu, o[k], d, 16);
    }

    if (i == 0) {
        float inv = 1.0f / lw;
        float* dst = g_attnout + ((size_t)(b * CS + s)) * CD + h * CHD;
        #pragma unroll
        for (int k = 0; k < CHD; k += 4) {
            float4 w;
            w.x = o[k] * inv; w.y = o[k + 1] * inv;
            w.z = o[k + 2] * inv; w.w = o[k + 3] * inv;
            *(float4*)(dst + k) = w;
        }
    }
}

// ---------------------------------------------------------------------------
extern "C" void kernel_launch(void* const* d_in, const int* in_sizes, int n_in,
                              void* d_out, int out_size)
{
    const float* x    = (const float*)d_in[0];
    const float* Wqkv = (const float*)d_in[1];
    const float* bqkv = (const float*)d_in[2];
    const float* Wout = (const float*)d_in[3];
    const float* bout = (const float*)d_in[4];
    float* out = (float*)d_out;

    // 1) head-sum the K/V weights+biases (linearity of the head reduction)
    prep_k<<<512, 256>>>(Wqkv, bqkv);
    // 2) fused q + kv_sum GEMM: N = 1024 (q) + 128 (k_sum|v_sum)
    sgemm_k<0><<<dim3(9, 32), 256>>>(x, Wqkv, bqkv, nullptr);
    // 3) causal flash attention over shared-key heads
    attn_k<<<dim3(CS, CB), 256>>>();
    // 4) output projection
    sgemm_k<1><<<dim3(8, 32), 256>>>(nullptr, Wout, bout, out);
}

// round 8
// speedup vs baseline: 1.3411x; 1.3386x over previous
#include <cuda_runtime.h>

// Problem constants
#define CB 2
#define CS 2048
#define CD 1024
#define CH 16
#define CHD 64
#define CM (CB*CS)   // 4096 tokens

// Scratch (allocation-free rule: __device__ globals)
__device__ float g_q[(size_t)CM * CD];        // 16 MB
__device__ float g_kvsum[(size_t)CM * 128];   // 2 MB  (cols 0..63 = k_sum, 64..127 = v_sum)
__device__ float g_attnout[(size_t)CM * CD];  // 16 MB
__device__ float g_Wkv[128 * CD];             // head-summed K/V weights
__device__ float g_bkv[128];

// ---------------------------------------------------------------------------
// Kernel 1: reduce Wqkv over heads -> Wk_sum (rows 0..63), Wv_sum (rows 64..127)
// ---------------------------------------------------------------------------
__global__ __launch_bounds__(256) void prep_k(const float* __restrict__ Wqkv,
                                              const float* __restrict__ bqkv)
{
    int idx = blockIdx.x * 256 + threadIdx.x;
    if (idx < 128 * 1024) {
        int r = idx >> 10;          // 0..127
        int c = idx & 1023;
        int rr = r & 63;
        int base = (r < 64 ? 1024 : 2048) + rr;
        float sum = 0.f;
        #pragma unroll
        for (int h = 0; h < 16; h++)
            sum += Wqkv[(size_t)(base + h * 64) * CD + c];
        g_Wkv[(size_t)r * CD + c] = sum;
    }
    if (idx < 128) {
        int rr = idx & 63;
        int base = (idx < 64 ? 1024 : 2048) + rr;
        float s = 0.f;
        #pragma unroll
        for (int h = 0; h < 16; h++)
            s += bqkv[base + h * 64];
        g_bkv[idx] = s;
    }
}

// ---------------------------------------------------------------------------
// SGEMM: C[m,n] = bias[n] + sum_k A[m,k] * B[n,k]   (both K-contiguous, "NT")
// BM=BN=128, BK=16, 256 threads, 8x8 per thread.
// MODE 0: A=x, N=1152 (cols <1024 from Wqkv -> g_q; cols >=1024 from g_Wkv -> g_kvsum)
// MODE 1: A=g_attnout, B=Wout, C=d_out
// ---------------------------------------------------------------------------
template<int MODE>
__global__ __launch_bounds__(256) void sgemm_k(const float* __restrict__ A,
                                               const float* __restrict__ Bw,
                                               const float* __restrict__ bias,
                                               float* __restrict__ Cout)
{
    const int K = CD;
    const int n0 = blockIdx.x * 128;
    const int m0 = blockIdx.y * 128;

    const float* Ap = (MODE == 0) ? A : g_attnout;
    const float* Bp;
    const float* bp;
    if (MODE == 0 && n0 >= CD) { Bp = g_Wkv; bp = g_bkv; }
    else                       { Bp = Bw + (size_t)n0 * K; bp = bias + n0; }

    __shared__ float As[16][132];
    __shared__ float Bs[16][132];

    const int tid = threadIdx.x;
    const int tx = tid & 15;
    const int ty = tid >> 4;

    float acc[8][8];
    #pragma unroll
    for (int i = 0; i < 8; i++)
        #pragma unroll
        for (int j = 0; j < 8; j++) acc[i][j] = 0.f;

    const float* Abase = Ap + (size_t)m0 * K;

    for (int k0 = 0; k0 < K; k0 += 16) {
        #pragma unroll
        for (int ii = 0; ii < 2; ii++) {
            int f = tid + ii * 256;          // 0..511
            int row = f >> 2;                // 0..127
            int c4 = (f & 3) << 2;           // 0,4,8,12
            float4 av = *(const float4*)(Abase + (size_t)row * K + k0 + c4);
            As[c4 + 0][row] = av.x; As[c4 + 1][row] = av.y;
            As[c4 + 2][row] = av.z; As[c4 + 3][row] = av.w;
            float4 bv = *(const float4*)(Bp + (size_t)row * K + k0 + c4);
            Bs[c4 + 0][row] = bv.x; Bs[c4 + 1][row] = bv.y;
            Bs[c4 + 2][row] = bv.z; Bs[c4 + 3][row] = bv.w;
        }
        __syncthreads();
        #pragma unroll
        for (int kk = 0; kk < 16; kk++) {
            float4 a0 = *(const float4*)&As[kk][ty * 8];
            float4 a1 = *(const float4*)&As[kk][ty * 8 + 4];
            float4 b0 = *(const float4*)&Bs[kk][tx * 8];
            float4 b1 = *(const float4*)&Bs[kk][tx * 8 + 4];
            float a[8] = {a0.x, a0.y, a0.z, a0.w, a1.x, a1.y, a1.z, a1.w};
            float b[8] = {b0.x, b0.y, b0.z, b0.w, b1.x, b1.y, b1.z, b1.w};
            #pragma unroll
            for (int i = 0; i < 8; i++)
                #pragma unroll
                for (int j = 0; j < 8; j++)
                    acc[i][j] += a[i] * b[j];
        }
        __syncthreads();
    }

    #pragma unroll
    for (int i = 0; i < 8; i++) {
        int m = m0 + ty * 8 + i;
        #pragma unroll
        for (int j = 0; j < 8; j += 4) {
            int nl = tx * 8 + j;
            float4 v;
            v.x = acc[i][j + 0] + bp[nl + 0];
            v.y = acc[i][j + 1] + bp[nl + 1];
            v.z = acc[i][j + 2] + bp[nl + 2];
            v.w = acc[i][j + 3] + bp[nl + 3];
            if (MODE == 0) {
                if (n0 < CD)
                    *(float4*)&g_q[(size_t)m * CD + n0 + nl] = v;
                else
                    *(float4*)&g_kvsum[(size_t)m * 128 + nl] = v;
            } else {
                *(float4*)&Cout[(size_t)m * CD + n0 + nl] = v;
            }
        }
    }
}

// ---------------------------------------------------------------------------
// Kernel 3: flash attention, GEMM-style.
// Row index r = s*16+h is CONTIGUOUS in g_q/g_attnout, so this is plain causal
// flash attention: Q'(BM=128 rows = 8 s x 16 h, 64 dims) vs 64-key tiles.
// 256 threads = 32 row-groups (ty) x 8 col-lanes (tx); thread tile 4x8.
// A-operands (q and P) live in registers, broadcast across the 8 tx lanes via
// shfl width=8 -> outer-product FMAs, no P smem round trip.
// ---------------------------------------------------------------------------
__global__ __launch_bounds__(256, 2) void attn_k()
{
    const int b  = blockIdx.y;
    const int s0 = blockIdx.x * 8;           // 8 s-values per block
    const int tid = threadIdx.x;
    const int ty = tid >> 3;                 // 0..31 (row group of 4)
    const int tx = tid & 7;                  // 0..7  (col group of 8)
    const int s_row = s0 + (ty >> 2);        // the s for ALL 4 rows of this thread

    __shared__ float ksT[64][68];            // [k dim][t], transposed
    __shared__ float vsm[64][68];            // [t][d dim], natural

    // q[ri][ci]: rows r = ty*4+ri (global row s0*16 + r), dims tx*8+ci
    float q[4][8];
    {
        const float* qb = g_q + (size_t)b * CS * CD + (size_t)(s0 * 16) * 64;
        #pragma unroll
        for (int ri = 0; ri < 4; ri++) {
            const float* p = qb + (size_t)(ty * 4 + ri) * 64 + tx * 8;
            float4 u = *(const float4*)p;
            float4 w = *(const float4*)(p + 4);
            q[ri][0] = u.x; q[ri][1] = u.y; q[ri][2] = u.z; q[ri][3] = u.w;
            q[ri][4] = w.x; q[ri][5] = w.y; q[ri][6] = w.z; q[ri][7] = w.w;
        }
    }

    float o[4][8];
    #pragma unroll
    for (int ri = 0; ri < 4; ri++)
        #pragma unroll
        for (int ci = 0; ci < 8; ci++) o[ri][ci] = 0.f;
    float mrow[4] = {-1e30f, -1e30f, -1e30f, -1e30f};
    float lrow[4] = {0.f, 0.f, 0.f, 0.f};
    const float scale = 0.125f;              // 1/sqrt(64)

    const int ntile = ((s0 + 7) >> 6) + 1;

    for (int tt = 0; tt < ntile; tt++) {
        const int t0 = tt * 64;
        __syncthreads();
        // Load K (transposed) and V (natural). t0+63 <= S-1 always: no bounds.
        {
            const float* kvb = g_kvsum + ((size_t)(b * CS + t0)) * 128;
            #pragma unroll
            for (int ii = 0; ii < 4; ii++) {
                int f = tid + ii * 256;           // 0..1023
                int tr = f >> 4;                  // 0..63
                int c4 = (f & 15) << 2;           // 0..60
                float4 kv = *(const float4*)(kvb + (size_t)tr * 128 + c4);
                ksT[c4 + 0][tr] = kv.x; ksT[c4 + 1][tr] = kv.y;
                ksT[c4 + 2][tr] = kv.z; ksT[c4 + 3][tr] = kv.w;
                float4 vv = *(const float4*)(kvb + (size_t)tr * 128 + 64 + c4);
                *(float4*)&vsm[tr][c4] = vv;
            }
        }
        __syncthreads();

        // ---- GEMM1: sc[4][8] = Q . K^T for this tile ----
        float sc[4][8];
        #pragma unroll
        for (int ri = 0; ri < 4; ri++)
            #pragma unroll
            for (int ci = 0; ci < 8; ci++) sc[ri][ci] = 0.f;

        #pragma unroll 2
        for (int kg = 0; kg < 8; kg++) {
            #pragma unroll
            for (int kc = 0; kc < 8; kc++) {
                const int k = kg * 8 + kc;
                float a0 = __shfl_sync(0xffffffffu, q[0][kc], kg, 8);
                float a1 = __shfl_sync(0xffffffffu, q[1][kc], kg, 8);
                float a2 = __shfl_sync(0xffffffffu, q[2][kc], kg, 8);
                float a3 = __shfl_sync(0xffffffffu, q[3][kc], kg, 8);
                float4 b0 = *(const float4*)&ksT[k][tx * 8];
                float4 b1 = *(const float4*)&ksT[k][tx * 8 + 4];
                float bb[8] = {b0.x, b0.y, b0.z, b0.w, b1.x, b1.y, b1.z, b1.w};
                #pragma unroll
                for (int ci = 0; ci < 8; ci++) {
                    sc[0][ci] += a0 * bb[ci];
                    sc[1][ci] += a1 * bb[ci];
                    sc[2][ci] += a2 * bb[ci];
                    sc[3][ci] += a3 * bb[ci];
                }
            }
        }

        // ---- scale + causal mask (t <= s_row) ----
        #pragma unroll
        for (int ci = 0; ci < 8; ci++) {
            const int t = t0 + tx * 8 + ci;
            const bool valid = (t <= s_row);
            #pragma unroll
            for (int ri = 0; ri < 4; ri++)
                sc[ri][ci] = valid ? sc[ri][ci] * scale : -1e30f;
        }

        // ---- online softmax ----
        float rm[4];
        #pragma unroll
        for (int ri = 0; ri < 4; ri++) {
            float v = sc[ri][0];
            #pragma unroll
            for (int ci = 1; ci < 8; ci++) v = fmaxf(v, sc[ri][ci]);
            v = fmaxf(v, __shfl_xor_sync(0xffffffffu, v, 4, 8));
            v = fmaxf(v, __shfl_xor_sync(0xffffffffu, v, 2, 8));
            v = fmaxf(v, __shfl_xor_sync(0xffffffffu, v, 1, 8));
            rm[ri] = v;
        }
        #pragma unroll
        for (int ri = 0; ri < 4; ri++) {
            float mn = fmaxf(mrow[ri], rm[ri]);
            float corr = __expf(mrow[ri] - mn);
            mrow[ri] = mn;
            lrow[ri] *= corr;
            #pragma unroll
            for (int ci = 0; ci < 8; ci++) o[ri][ci] *= corr;
            float rs = 0.f;
            #pragma unroll
            for (int ci = 0; ci < 8; ci++) {
                sc[ri][ci] = __expf(sc[ri][ci] - mn);
                rs += sc[ri][ci];
            }
            rs += __shfl_xor_sync(0xffffffffu, rs, 4, 8);
            rs += __shfl_xor_sync(0xffffffffu, rs, 2, 8);
            rs += __shfl_xor_sync(0xffffffffu, rs, 1, 8);
            lrow[ri] += rs;
        }

        // ---- GEMM2: o += P . V  (P broadcast from registers via shfl) ----
        #pragma unroll 2
        for (int tg = 0; tg < 8; tg++) {
            #pragma unroll
            for (int tc = 0; tc < 8; tc++) {
                const int t = tg * 8 + tc;
                float a0 = __shfl_sync(0xffffffffu, sc[0][tc], tg, 8);
                float a1 = __shfl_sync(0xffffffffu, sc[1][tc], tg, 8);
                float a2 = __shfl_sync(0xffffffffu, sc[2][tc], tg, 8);
                float a3 = __shfl_sync(0xffffffffu, sc[3][tc], tg, 8);
                float4 v0 = *(const float4*)&vsm[t][tx * 8];
                float4 v1 = *(const float4*)&vsm[t][tx * 8 + 4];
                float vv[8] = {v0.x, v0.y, v0.z, v0.w, v1.x, v1.y, v1.z, v1.w};
                #pragma unroll
                for (int ci = 0; ci < 8; ci++) {
                    o[0][ci] += a0 * vv[ci];
                    o[1][ci] += a1 * vv[ci];
                    o[2][ci] += a2 * vv[ci];
                    o[3][ci] += a3 * vv[ci];
                }
            }
        }
    }

    // ---- normalize + write ----
    float* ob = g_attnout + (size_t)b * CS * CD + (size_t)(s0 * 16) * 64;
    #pragma unroll
    for (int ri = 0; ri < 4; ri++) {
        float inv = 1.0f / lrow[ri];
        float* dst = ob + (size_t)(ty * 4 + ri) * 64 + tx * 8;
        float4 w0, w1;
        w0.x = o[ri][0] * inv; w0.y = o[ri][1] * inv;
        w0.z = o[ri][2] * inv; w0.w = o[ri][3] * inv;
        w1.x = o[ri][4] * inv; w1.y = o[ri][5] * inv;
        w1.z = o[ri][6] * inv; w1.w = o[ri][7] * inv;
        *(float4*)dst = w0;
        *(float4*)(dst + 4) = w1;
    }
}

// ---------------------------------------------------------------------------
extern "C" void kernel_launch(void* const* d_in, const int* in_sizes, int n_in,
                              void* d_out, int out_size)
{
    const float* x    = (const float*)d_in[0];
    const float* Wqkv = (const float*)d_in[1];
    const float* bqkv = (const float*)d_in[2];
    const float* Wout = (const float*)d_in[3];
    const float* bout = (const float*)d_in[4];
    float* out = (float*)d_out;

    // 1) head-sum the K/V weights+biases (linearity of the head reduction)
    prep_k<<<512, 256>>>(Wqkv, bqkv);
    // 2) fused q + kv_sum GEMM: N = 1024 (q) + 128 (k_sum|v_sum)
    sgemm_k<0><<<dim3(9, 32), 256>>>(x, Wqkv, bqkv, nullptr);
    // 3) causal flash attention, GEMM-style register tiling
    attn_k<<<dim3(CS / 8, CB), 256>>>();
    // 4) output projection
    sgemm_k<1><<<dim3(8, 32), 256>>>(nullptr, Wout, bout, out);
}

// round 11
// speedup vs baseline: 1.4427x; 1.0758x over previous
#include <cuda_runtime.h>
#include <cstdint>

// Problem constants
#define CB 2
#define CS 2048
#define CD 1024
#define CH 16
#define CHD 64
#define CM (CB*CS)   // 4096 tokens

// Scratch (allocation-free rule: __device__ globals)
__device__ float g_q[(size_t)CM * CD];        // 16 MB
__device__ float g_kvsum[(size_t)CM * 128];   // 2 MB  (cols 0..63 = k_sum, 64..127 = v_sum)
__device__ float g_attnout[(size_t)CM * CD];  // 16 MB
__device__ float g_Wkv[128 * CD];             // head-summed K/V weights
__device__ float g_bkv[128];

// ---------------------------------------------------------------------------
// helpers
// ---------------------------------------------------------------------------
__device__ __forceinline__ float tf32_rna(float x) {
    uint32_t r;
    asm("cvt.rna.tf32.f32 %0, %1;" : "=r"(r) : "f"(x));
    return __uint_as_float(r);
}
// mma.sync m16n8k8 tf32 (portable path: no sm_103a-only ISA)
__device__ __forceinline__ void mma8(float* c, const uint32_t* a, const uint32_t* b) {
    asm volatile(
        "mma.sync.aligned.m16n8k8.row.col.f32.tf32.tf32.f32 "
        "{%0,%1,%2,%3}, {%4,%5,%6,%7}, {%8,%9}, {%0,%1,%2,%3};"
        : "+f"(c[0]), "+f"(c[1]), "+f"(c[2]), "+f"(c[3])
        : "r"(a[0]), "r"(a[1]), "r"(a[2]), "r"(a[3]), "r"(b[0]), "r"(b[1]));
}

// ---------------------------------------------------------------------------
// Kernel 1: reduce Wqkv over heads -> Wk_sum (rows 0..63), Wv_sum (rows 64..127)
// ---------------------------------------------------------------------------
__global__ __launch_bounds__(256) void prep_k(const float* __restrict__ Wqkv,
                                              const float* __restrict__ bqkv)
{
    int idx = blockIdx.x * 256 + threadIdx.x;
    if (idx < 128 * 1024) {
        int r = idx >> 10;          // 0..127
        int c = idx & 1023;
        int rr = r & 63;
        int base = (r < 64 ? 1024 : 2048) + rr;
        float sum = 0.f;
        #pragma unroll
        for (int h = 0; h < 16; h++)
            sum += Wqkv[(size_t)(base + h * 64) * CD + c];
        g_Wkv[(size_t)r * CD + c] = sum;
    }
    if (idx < 128) {
        int rr = idx & 63;
        int base = (idx < 64 ? 1024 : 2048) + rr;
        float s = 0.f;
        #pragma unroll
        for (int h = 0; h < 16; h++)
            s += bqkv[base + h * 64];
        g_bkv[idx] = s;
    }
}

// ---------------------------------------------------------------------------
// tf32 mma.sync GEMM (3xTF32): C[m,n] = bias[n] + sum_k A[m,k]*B[n,k]  ("NT")
// BM=BN=128, BK=32. 8 warps = 2(m) x 4(n); warp tile 64x32; frags m16n8k8.
// hi/lo split done once per tile by loader threads into 4 smem planes.
// MODE 0: A=x, N=1152 (cols <1024 -> g_q; cols >=1024 from g_Wkv -> g_kvsum)
// MODE 1: A=g_attnout, B=Wout, C=d_out
// ---------------------------------------------------------------------------
#define LDP 36                              // smem row stride (floats)
#define GEMM_SMEM_BYTES (4 * 128 * LDP * 4) // 73728

template<int MODE>
__global__ __launch_bounds__(256) void gemm_mma(const float* __restrict__ A,
                                                const float* __restrict__ Bw,
                                                const float* __restrict__ bias,
                                                float* __restrict__ Cout)
{
    extern __shared__ float sm[];
    float* Ash = sm;                 // [128][LDP] hi
    float* Asl = sm + 128 * LDP;     // lo
    float* Bsh = sm + 2 * 128 * LDP;
    float* Bsl = sm + 3 * 128 * LDP;

    const int tid = threadIdx.x;
    const int wid = tid >> 5;
    const int lane = tid & 31;
    const int grp = lane >> 2;       // 0..7
    const int q   = lane & 3;        // 0..3
    const int warp_m = wid >> 2;     // 0..1
    const int warp_n = wid & 3;      // 0..3

    const int n0 = blockIdx.x * 128;
    const int m0 = blockIdx.y * 128;

    const float* Ap = (MODE == 0) ? A : g_attnout;
    const float* Bp;
    const float* bp;
    if (MODE == 0 && n0 >= CD) { Bp = g_Wkv; bp = g_bkv; }
    else                       { Bp = Bw + (size_t)n0 * CD; bp = bias + n0; }
    const float* Abase = Ap + (size_t)m0 * CD;

    float acc[4][4][4];
    #pragma unroll
    for (int mt = 0; mt < 4; mt++)
        #pragma unroll
        for (int nt = 0; nt < 4; nt++)
            #pragma unroll
            for (int r = 0; r < 4; r++) acc[mt][nt][r] = 0.f;

    // loader roles: 4 float4 per operand per tile
    int rowv[4], colv[4];
    #pragma unroll
    for (int i = 0; i < 4; i++) {
        int f = tid + i * 256;      // 0..1023
        rowv[i] = f >> 3;           // 0..127
        colv[i] = (f & 7) << 2;     // 0..28
    }

    float4 ra[4], rb[4];
    #pragma unroll
    for (int i = 0; i < 4; i++) {
        ra[i] = *(const float4*)(Abase + (size_t)rowv[i] * CD + colv[i]);
        rb[i] = *(const float4*)(Bp    + (size_t)rowv[i] * CD + colv[i]);
    }

    for (int kt = 0; kt < 32; kt++) {
        // split + store current tile
        #pragma unroll
        for (int i = 0; i < 4; i++) {
            const int so = rowv[i] * LDP + colv[i];
            float4 h, l;
            h.x = tf32_rna(ra[i].x); l.x = tf32_rna(ra[i].x - h.x);
            h.y = tf32_rna(ra[i].y); l.y = tf32_rna(ra[i].y - h.y);
            h.z = tf32_rna(ra[i].z); l.z = tf32_rna(ra[i].z - h.z);
            h.w = tf32_rna(ra[i].w); l.w = tf32_rna(ra[i].w - h.w);
            *(float4*)&Ash[so] = h;  *(float4*)&Asl[so] = l;
            h.x = tf32_rna(rb[i].x); l.x = tf32_rna(rb[i].x - h.x);
            h.y = tf32_rna(rb[i].y); l.y = tf32_rna(rb[i].y - h.y);
            h.z = tf32_rna(rb[i].z); l.z = tf32_rna(rb[i].z - h.z);
            h.w = tf32_rna(rb[i].w); l.w = tf32_rna(rb[i].w - h.w);
            *(float4*)&Bsh[so] = h;  *(float4*)&Bsl[so] = l;
        }
        __syncthreads();

        // prefetch next tile (global latency hidden under MMA)
        if (kt < 31) {
            const int k0 = (kt + 1) * 32;
            #pragma unroll
            for (int i = 0; i < 4; i++) {
                ra[i] = *(const float4*)(Abase + (size_t)rowv[i] * CD + k0 + colv[i]);
                rb[i] = *(const float4*)(Bp    + (size_t)rowv[i] * CD + k0 + colv[i]);
            }
        }

        #pragma unroll
        for (int ks = 0; ks < 4; ks++) {
            const int k = ks * 8 + q;
            uint32_t ah[4][4], al[4][4], bh[4][2], bl[4][2];
            #pragma unroll
            for (int mt = 0; mt < 4; mt++) {
                const int mb = (warp_m * 64 + mt * 16 + grp) * LDP;
                ah[mt][0] = __float_as_uint(Ash[mb + k]);
                ah[mt][1] = __float_as_uint(Ash[mb + 8 * LDP + k]);
                ah[mt][2] = __float_as_uint(Ash[mb + k + 4]);
                ah[mt][3] = __float_as_uint(Ash[mb + 8 * LDP + k + 4]);
                al[mt][0] = __float_as_uint(Asl[mb + k]);
                al[mt][1] = __float_as_uint(Asl[mb + 8 * LDP + k]);
                al[mt][2] = __float_as_uint(Asl[mb + k + 4]);
                al[mt][3] = __float_as_uint(Asl[mb + 8 * LDP + k + 4]);
            }
            #pragma unroll
            for (int nt = 0; nt < 4; nt++) {
                const int nb = (warp_n * 32 + nt * 8 + grp) * LDP;
                bh[nt][0] = __float_as_uint(Bsh[nb + k]);
                bh[nt][1] = __float_as_uint(Bsh[nb + k + 4]);
                bl[nt][0] = __float_as_uint(Bsl[nb + k]);
                bl[nt][1] = __float_as_uint(Bsl[nb + k + 4]);
            }
            #pragma unroll
            for (int mt = 0; mt < 4; mt++)
                #pragma unroll
                for (int nt = 0; nt < 4; nt++) {
                    mma8(acc[mt][nt], ah[mt], bh[nt]);
                    mma8(acc[mt][nt], ah[mt], bl[nt]);
                    mma8(acc[mt][nt], al[mt], bh[nt]);
                }
        }
        __syncthreads();
    }

    // epilogue: bias + write (float2 per fragment half-row)
    #pragma unroll
    for (int mt = 0; mt < 4; mt++) {
        const int m = m0 + warp_m * 64 + mt * 16 + grp;
        #pragma unroll
        for (int nt = 0; nt < 4; nt++) {
            const int nl = warp_n * 32 + nt * 8 + q * 2;
            float2 v0, v1;
            v0.x = acc[mt][nt][0] + bp[nl];
            v0.y = acc[mt][nt][1] + bp[nl + 1];
            v1.x = acc[mt][nt][2] + bp[nl];
            v1.y = acc[mt][nt][3] + bp[nl + 1];
            if (MODE == 0) {
                if (n0 < CD) {
                    *(float2*)&g_q[(size_t)m * CD + n0 + nl] = v0;
                    *(float2*)&g_q[(size_t)(m + 8) * CD + n0 + nl] = v1;
                } else {
                    *(float2*)&g_kvsum[(size_t)m * 128 + nl] = v0;
                    *(float2*)&g_kvsum[(size_t)(m + 8) * 128 + nl] = v1;
                }
            } else {
                *(float2*)&Cout[(size_t)m * CD + n0 + nl] = v0;
                *(float2*)&Cout[(size_t)(m + 8) * CD + n0 + nl] = v1;
            }
        }
    }
}

// ---------------------------------------------------------------------------
// Kernel 3: flash attention, GEMM-style register tiling (unchanged, passing).
// ---------------------------------------------------------------------------
__global__ __launch_bounds__(256, 2) void attn_k()
{
    const int b  = blockIdx.y;
    const int s0 = blockIdx.x * 8;           // 8 s-values per block
    const int tid = threadIdx.x;
    const int ty = tid >> 3;                 // 0..31 (row group of 4)
    const int tx = tid & 7;                  // 0..7  (col group of 8)
    const int s_row = s0 + (ty >> 2);        // the s for ALL 4 rows of this thread

    __shared__ float ksT[64][68];            // [k dim][t], transposed
    __shared__ float vsm[64][68];            // [t][d dim], natural

    float q[4][8];
    {
        const float* qb = g_q + (size_t)b * CS * CD + (size_t)(s0 * 16) * 64;
        #pragma unroll
        for (int ri = 0; ri < 4; ri++) {
            const float* p = qb + (size_t)(ty * 4 + ri) * 64 + tx * 8;
            float4 u = *(const float4*)p;
            float4 w = *(const float4*)(p + 4);
            q[ri][0] = u.x; q[ri][1] = u.y; q[ri][2] = u.z; q[ri][3] = u.w;
            q[ri][4] = w.x; q[ri][5] = w.y; q[ri][6] = w.z; q[ri][7] = w.w;
        }
    }

    float o[4][8];
    #pragma unroll
    for (int ri = 0; ri < 4; ri++)
        #pragma unroll
        for (int ci = 0; ci < 8; ci++) o[ri][ci] = 0.f;
    float mrow[4] = {-1e30f, -1e30f, -1e30f, -1e30f};
    float lrow[4] = {0.f, 0.f, 0.f, 0.f};
    const float scale = 0.125f;              // 1/sqrt(64)

    const int ntile = ((s0 + 7) >> 6) + 1;

    for (int tt = 0; tt < ntile; tt++) {
        const int t0 = tt * 64;
        __syncthreads();
        {
            const float* kvb = g_kvsum + ((size_t)(b * CS + t0)) * 128;
            #pragma unroll
            for (int ii = 0; ii < 4; ii++) {
                int f = tid + ii * 256;           // 0..1023
                int tr = f >> 4;                  // 0..63
                int c4 = (f & 15) << 2;           // 0..60
                float4 kv = *(const float4*)(kvb + (size_t)tr * 128 + c4);
                ksT[c4 + 0][tr] = kv.x; ksT[c4 + 1][tr] = kv.y;
                ksT[c4 + 2][tr] = kv.z; ksT[c4 + 3][tr] = kv.w;
                float4 vv = *(const float4*)(kvb + (size_t)tr * 128 + 64 + c4);
                *(float4*)&vsm[tr][c4] = vv;
            }
        }
        __syncthreads();

        float sc[4][8];
        #pragma unroll
        for (int ri = 0; ri < 4; ri++)
            #pragma unroll
            for (int ci = 0; ci < 8; ci++) sc[ri][ci] = 0.f;

        #pragma unroll 2
        for (int kg = 0; kg < 8; kg++) {
            #pragma unroll
            for (int kc = 0; kc < 8; kc++) {
                const int k = kg * 8 + kc;
                float a0 = __shfl_sync(0xffffffffu, q[0][kc], kg, 8);
                float a1 = __shfl_sync(0xffffffffu, q[1][kc], kg, 8);
                float a2 = __shfl_sync(0xffffffffu, q[2][kc], kg, 8);
                float a3 = __shfl_sync(0xffffffffu, q[3][kc], kg, 8);
                float4 b0 = *(const float4*)&ksT[k][tx * 8];
                float4 b1 = *(const float4*)&ksT[k][tx * 8 + 4];
                float bb[8] = {b0.x, b0.y, b0.z, b0.w, b1.x, b1.y, b1.z, b1.w};
                #pragma unroll
                for (int ci = 0; ci < 8; ci++) {
                    sc[0][ci] += a0 * bb[ci];
                    sc[1][ci] += a1 * bb[ci];
                    sc[2][ci] += a2 * bb[ci];
                    sc[3][ci] += a3 * bb[ci];
                }
            }
        }

        #pragma unroll
        for (int ci = 0; ci < 8; ci++) {
            const int t = t0 + tx * 8 + ci;
            const bool valid = (t <= s_row);
            #pragma unroll
            for (int ri = 0; ri < 4; ri++)
                sc[ri][ci] = valid ? sc[ri][ci] * scale : -1e30f;
        }

        float rm[4];
        #pragma unroll
        for (int ri = 0; ri < 4; ri++) {
            float v = sc[ri][0];
            #pragma unroll
            for (int ci = 1; ci < 8; ci++) v = fmaxf(v, sc[ri][ci]);
            v = fmaxf(v, __shfl_xor_sync(0xffffffffu, v, 4, 8));
            v = fmaxf(v, __shfl_xor_sync(0xffffffffu, v, 2, 8));
            v = fmaxf(v, __shfl_xor_sync(0xffffffffu, v, 1, 8));
            rm[ri] = v;
        }
        #pragma unroll
        for (int ri = 0; ri < 4; ri++) {
            float mn = fmaxf(mrow[ri], rm[ri]);
            float corr = __expf(mrow[ri] - mn);
            mrow[ri] = mn;
            lrow[ri] *= corr;
            #pragma unroll
            for (int ci = 0; ci < 8; ci++) o[ri][ci] *= corr;
            float rs = 0.f;
            #pragma unroll
            for (int ci = 0; ci < 8; ci++) {
                sc[ri][ci] = __expf(sc[ri][ci] - mn);
                rs += sc[ri][ci];
            }
            rs += __shfl_xor_sync(0xffffffffu, rs, 4, 8);
            rs += __shfl_xor_sync(0xffffffffu, rs, 2, 8);
            rs += __shfl_xor_sync(0xffffffffu, rs, 1, 8);
            lrow[ri] += rs;
        }

        #pragma unroll 2
        for (int tg = 0; tg < 8; tg++) {
            #pragma unroll
            for (int tc = 0; tc < 8; tc++) {
                const int t = tg * 8 + tc;
                float a0 = __shfl_sync(0xffffffffu, sc[0][tc], tg, 8);
                float a1 = __shfl_sync(0xffffffffu, sc[1][tc], tg, 8);
                float a2 = __shfl_sync(0xffffffffu, sc[2][tc], tg, 8);
                float a3 = __shfl_sync(0xffffffffu, sc[3][tc], tg, 8);
                float4 v0 = *(const float4*)&vsm[t][tx * 8];
                float4 v1 = *(const float4*)&vsm[t][tx * 8 + 4];
                float vv[8] = {v0.x, v0.y, v0.z, v0.w, v1.x, v1.y, v1.z, v1.w};
                #pragma unroll
                for (int ci = 0; ci < 8; ci++) {
                    o[0][ci] += a0 * vv[ci];
                    o[1][ci] += a1 * vv[ci];
                    o[2][ci] += a2 * vv[ci];
                    o[3][ci] += a3 * vv[ci];
                }
            }
        }
    }

    float* ob = g_attnout + (size_t)b * CS * CD + (size_t)(s0 * 16) * 64;
    #pragma unroll
    for (int ri = 0; ri < 4; ri++) {
        float inv = 1.0f / lrow[ri];
        float* dst = ob + (size_t)(ty * 4 + ri) * 64 + tx * 8;
        float4 w0, w1;
        w0.x = o[ri][0] * inv; w0.y = o[ri][1] * inv;
        w0.z = o[ri][2] * inv; w0.w = o[ri][3] * inv;
        w1.x = o[ri][4] * inv; w1.y = o[ri][5] * inv;
        w1.z = o[ri][6] * inv; w1.w = o[ri][7] * inv;
        *(float4*)dst = w0;
        *(float4*)(dst + 4) = w1;
    }
}

// ---------------------------------------------------------------------------
extern "C" void kernel_launch(void* const* d_in, const int* in_sizes, int n_in,
                              void* d_out, int out_size)
{
    const float* x    = (const float*)d_in[0];
    const float* Wqkv = (const float*)d_in[1];
    const float* bqkv = (const float*)d_in[2];
    const float* Wout = (const float*)d_in[3];
    const float* bout = (const float*)d_in[4];
    float* out = (float*)d_out;

    cudaFuncSetAttribute(gemm_mma<0>, cudaFuncAttributeMaxDynamicSharedMemorySize,
                         GEMM_SMEM_BYTES);
    cudaFuncSetAttribute(gemm_mma<1>, cudaFuncAttributeMaxDynamicSharedMemorySize,
                         GEMM_SMEM_BYTES);

    // 1) head-sum the K/V weights+biases (linearity of the head reduction)
    prep_k<<<512, 256>>>(Wqkv, bqkv);
    // 2) fused q + kv_sum GEMM on tensor cores (mma.sync tf32, 3xTF32)
    gemm_mma<0><<<dim3(9, 32), 256, GEMM_SMEM_BYTES>>>(x, Wqkv, bqkv, nullptr);
    // 3) causal flash attention, GEMM-style register tiling
    attn_k<<<dim3(CS / 8, CB), 256>>>();
    // 4) output projection on tensor cores (mma.sync tf32, 3xTF32)
    gemm_mma<1><<<dim3(8, 32), 256, GEMM_SMEM_BYTES>>>(nullptr, Wout, bout, out);
}

// round 12
// speedup vs baseline: 2.5844x; 1.7913x over previous
#include <cuda_runtime.h>
#include <cstdint>

// Problem constants
#define CB 2
#define CS 2048
#define CD 1024
#define CH 16
#define CHD 64
#define CM (CB*CS)   // 4096 tokens

// Scratch (allocation-free rule: __device__ globals)
__device__ float g_q[(size_t)CM * CD];        // 16 MB
__device__ float g_kvsum[(size_t)CM * 128];   // 2 MB  (cols 0..63 = k_sum, 64..127 = v_sum)
__device__ float g_attnout[(size_t)CM * CD];  // 16 MB
__device__ float g_Wkv[128 * CD];             // head-summed K/V weights
__device__ float g_bkv[128];

// ---------------------------------------------------------------------------
// helpers
// ---------------------------------------------------------------------------
__device__ __forceinline__ float tf32_rna(float x) {
    uint32_t r;
    asm("cvt.rna.tf32.f32 %0, %1;" : "=r"(r) : "f"(x));
    return __uint_as_float(r);
}
__device__ __forceinline__ void split_tf32(float x, uint32_t& h, uint32_t& l) {
    float hf = tf32_rna(x);
    h = __float_as_uint(hf);
    l = __float_as_uint(tf32_rna(x - hf));
}
// mma.sync m16n8k8 tf32 (portable path: no sm_103a-only ISA)
__device__ __forceinline__ void mma8(float* c, const uint32_t* a, const uint32_t* b) {
    asm volatile(
        "mma.sync.aligned.m16n8k8.row.col.f32.tf32.tf32.f32 "
        "{%0,%1,%2,%3}, {%4,%5,%6,%7}, {%8,%9}, {%0,%1,%2,%3};"
        : "+f"(c[0]), "+f"(c[1]), "+f"(c[2]), "+f"(c[3])
        : "r"(a[0]), "r"(a[1]), "r"(a[2]), "r"(a[3]), "r"(b[0]), "r"(b[1]));
}

// ---------------------------------------------------------------------------
// Kernel 1: reduce Wqkv over heads -> Wk_sum (rows 0..63), Wv_sum (rows 64..127)
// ---------------------------------------------------------------------------
__global__ __launch_bounds__(256) void prep_k(const float* __restrict__ Wqkv,
                                              const float* __restrict__ bqkv)
{
    int idx = blockIdx.x * 256 + threadIdx.x;
    if (idx < 128 * 1024) {
        int r = idx >> 10;          // 0..127
        int c = idx & 1023;
        int rr = r & 63;
        int base = (r < 64 ? 1024 : 2048) + rr;
        float sum = 0.f;
        #pragma unroll
        for (int h = 0; h < 16; h++)
            sum += Wqkv[(size_t)(base + h * 64) * CD + c];
        g_Wkv[(size_t)r * CD + c] = sum;
    }
    if (idx < 128) {
        int rr = idx & 63;
        int base = (idx < 64 ? 1024 : 2048) + rr;
        float s = 0.f;
        #pragma unroll
        for (int h = 0; h < 16; h++)
            s += bqkv[base + h * 64];
        g_bkv[idx] = s;
    }
}

// ---------------------------------------------------------------------------
// tf32 mma.sync GEMM (3xTF32) — unchanged from R11 (passing, 162-190us each)
// ---------------------------------------------------------------------------
#define LDP 36
#define GEMM_SMEM_BYTES (4 * 128 * LDP * 4)

template<int MODE>
__global__ __launch_bounds__(256) void gemm_mma(const float* __restrict__ A,
                                                const float* __restrict__ Bw,
                                                const float* __restrict__ bias,
                                                float* __restrict__ Cout)
{
    extern __shared__ float sm[];
    float* Ash = sm;
    float* Asl = sm + 128 * LDP;
    float* Bsh = sm + 2 * 128 * LDP;
    float* Bsl = sm + 3 * 128 * LDP;

    const int tid = threadIdx.x;
    const int wid = tid >> 5;
    const int lane = tid & 31;
    const int grp = lane >> 2;
    const int q   = lane & 3;
    const int warp_m = wid >> 2;
    const int warp_n = wid & 3;

    const int n0 = blockIdx.x * 128;
    const int m0 = blockIdx.y * 128;

    const float* Ap = (MODE == 0) ? A : g_attnout;
    const float* Bp;
    const float* bp;
    if (MODE == 0 && n0 >= CD) { Bp = g_Wkv; bp = g_bkv; }
    else                       { Bp = Bw + (size_t)n0 * CD; bp = bias + n0; }
    const float* Abase = Ap + (size_t)m0 * CD;

    float acc[4][4][4];
    #pragma unroll
    for (int mt = 0; mt < 4; mt++)
        #pragma unroll
        for (int nt = 0; nt < 4; nt++)
            #pragma unroll
            for (int r = 0; r < 4; r++) acc[mt][nt][r] = 0.f;

    int rowv[4], colv[4];
    #pragma unroll
    for (int i = 0; i < 4; i++) {
        int f = tid + i * 256;
        rowv[i] = f >> 3;
        colv[i] = (f & 7) << 2;
    }

    float4 ra[4], rb[4];
    #pragma unroll
    for (int i = 0; i < 4; i++) {
        ra[i] = *(const float4*)(Abase + (size_t)rowv[i] * CD + colv[i]);
        rb[i] = *(const float4*)(Bp    + (size_t)rowv[i] * CD + colv[i]);
    }

    for (int kt = 0; kt < 32; kt++) {
        #pragma unroll
        for (int i = 0; i < 4; i++) {
            const int so = rowv[i] * LDP + colv[i];
            float4 h, l;
            h.x = tf32_rna(ra[i].x); l.x = tf32_rna(ra[i].x - h.x);
            h.y = tf32_rna(ra[i].y); l.y = tf32_rna(ra[i].y - h.y);
            h.z = tf32_rna(ra[i].z); l.z = tf32_rna(ra[i].z - h.z);
            h.w = tf32_rna(ra[i].w); l.w = tf32_rna(ra[i].w - h.w);
            *(float4*)&Ash[so] = h;  *(float4*)&Asl[so] = l;
            h.x = tf32_rna(rb[i].x); l.x = tf32_rna(rb[i].x - h.x);
            h.y = tf32_rna(rb[i].y); l.y = tf32_rna(rb[i].y - h.y);
            h.z = tf32_rna(rb[i].z); l.z = tf32_rna(rb[i].z - h.z);
            h.w = tf32_rna(rb[i].w); l.w = tf32_rna(rb[i].w - h.w);
            *(float4*)&Bsh[so] = h;  *(float4*)&Bsl[so] = l;
        }
        __syncthreads();

        if (kt < 31) {
            const int k0 = (kt + 1) * 32;
            #pragma unroll
            for (int i = 0; i < 4; i++) {
                ra[i] = *(const float4*)(Abase + (size_t)rowv[i] * CD + k0 + colv[i]);
                rb[i] = *(const float4*)(Bp    + (size_t)rowv[i] * CD + k0 + colv[i]);
            }
        }

        #pragma unroll
        for (int ks = 0; ks < 4; ks++) {
            const int k = ks * 8 + q;
            uint32_t ah[4][4], al[4][4], bh[4][2], bl[4][2];
            #pragma unroll
            for (int mt = 0; mt < 4; mt++) {
                const int mb = (warp_m * 64 + mt * 16 + grp) * LDP;
                ah[mt][0] = __float_as_uint(Ash[mb + k]);
                ah[mt][1] = __float_as_uint(Ash[mb + 8 * LDP + k]);
                ah[mt][2] = __float_as_uint(Ash[mb + k + 4]);
                ah[mt][3] = __float_as_uint(Ash[mb + 8 * LDP + k + 4]);
                al[mt][0] = __float_as_uint(Asl[mb + k]);
                al[mt][1] = __float_as_uint(Asl[mb + 8 * LDP + k]);
                al[mt][2] = __float_as_uint(Asl[mb + k + 4]);
                al[mt][3] = __float_as_uint(Asl[mb + 8 * LDP + k + 4]);
            }
            #pragma unroll
            for (int nt = 0; nt < 4; nt++) {
                const int nb = (warp_n * 32 + nt * 8 + grp) * LDP;
                bh[nt][0] = __float_as_uint(Bsh[nb + k]);
                bh[nt][1] = __float_as_uint(Bsh[nb + k + 4]);
                bl[nt][0] = __float_as_uint(Bsl[nb + k]);
                bl[nt][1] = __float_as_uint(Bsl[nb + k + 4]);
            }
            #pragma unroll
            for (int mt = 0; mt < 4; mt++)
                #pragma unroll
                for (int nt = 0; nt < 4; nt++) {
                    mma8(acc[mt][nt], ah[mt], bh[nt]);
                    mma8(acc[mt][nt], ah[mt], bl[nt]);
                    mma8(acc[mt][nt], al[mt], bh[nt]);
                }
        }
        __syncthreads();
    }

    #pragma unroll
    for (int mt = 0; mt < 4; mt++) {
        const int m = m0 + warp_m * 64 + mt * 16 + grp;
        #pragma unroll
        for (int nt = 0; nt < 4; nt++) {
            const int nl = warp_n * 32 + nt * 8 + q * 2;
            float2 v0, v1;
            v0.x = acc[mt][nt][0] + bp[nl];
            v0.y = acc[mt][nt][1] + bp[nl + 1];
            v1.x = acc[mt][nt][2] + bp[nl];
            v1.y = acc[mt][nt][3] + bp[nl + 1];
            if (MODE == 0) {
                if (n0 < CD) {
                    *(float2*)&g_q[(size_t)m * CD + n0 + nl] = v0;
                    *(float2*)&g_q[(size_t)(m + 8) * CD + n0 + nl] = v1;
                } else {
                    *(float2*)&g_kvsum[(size_t)m * 128 + nl] = v0;
                    *(float2*)&g_kvsum[(size_t)(m + 8) * 128 + nl] = v1;
                }
            } else {
                *(float2*)&Cout[(size_t)m * CD + n0 + nl] = v0;
                *(float2*)&Cout[(size_t)(m + 8) * CD + n0 + nl] = v1;
            }
        }
    }
}

// ---------------------------------------------------------------------------
// Kernel 3: flash attention on tensor cores (mma.sync tf32, 3xTF32 both GEMMs).
// Block = 8 s-values x 16 heads = 128 Q' rows. Warp w owns s = s0+w (16 rows,
// one head per row) -> causal mask is warp-uniform per key column.
// K/V tiles (64 keys) hi/lo split in smem (stride 68: conflict-free B-frags).
// P round-trips through per-warp smem buffer for C-frag -> A-frag relayout.
// ---------------------------------------------------------------------------
#define AT_KHI 0
#define AT_KLO 4352          // 64*68
#define AT_VHI 8704
#define AT_VLO 13056
#define AT_PW  17408
#define ATTN_SMEM_BYTES ((17408 + 8 * 16 * 72) * 4)   // 106496

__global__ __launch_bounds__(256) void attn_tc()
{
    extern __shared__ float smf[];
    float* Khi = smf + AT_KHI;
    float* Klo = smf + AT_KLO;
    float* Vhi = smf + AT_VHI;
    float* Vlo = smf + AT_VLO;

    const int b   = blockIdx.y;
    const int s0  = blockIdx.x * 8;
    const int tid = threadIdx.x;
    const int w   = tid >> 5;
    const int lane = tid & 31;
    const int grp = lane >> 2;      // 0..7
    const int q   = lane & 3;       // 0..3
    const int s_w = s0 + w;         // this warp's s (rows = 16 heads of s_w)
    float* Pme = smf + AT_PW + w * (16 * 72);

    // ---- Q A-fragments (scaled by 1/sqrt(64), hi/lo split, live all tiles) ----
    uint32_t qh[8][4], ql[8][4];
    {
        const float* qb = g_q + (size_t)(b * CS + s_w) * 1024;
        #pragma unroll
        for (int kf = 0; kf < 8; kf++) {
            float a0 = 0.125f * qb[grp * 64 + kf * 8 + q];
            float a1 = 0.125f * qb[(grp + 8) * 64 + kf * 8 + q];
            float a2 = 0.125f * qb[grp * 64 + kf * 8 + q + 4];
            float a3 = 0.125f * qb[(grp + 8) * 64 + kf * 8 + q + 4];
            split_tf32(a0, qh[kf][0], ql[kf][0]);
            split_tf32(a1, qh[kf][1], ql[kf][1]);
            split_tf32(a2, qh[kf][2], ql[kf][2]);
            split_tf32(a3, qh[kf][3], ql[kf][3]);
        }
    }

    float acc[8][4];
    #pragma unroll
    for (int nf = 0; nf < 8; nf++)
        #pragma unroll
        for (int r = 0; r < 4; r++) acc[nf][r] = 0.f;
    float m0 = -1e30f, m1 = -1e30f, l0 = 0.f, l1 = 0.f;

    const int ntile = ((s0 + 7) >> 6) + 1;   // block-uniform (max over warps)
    const float* kvb = g_kvsum + (size_t)(b * CS) * 128;

    // prefetch tile 0 (8 float4 per thread = K+V 64x64 each)
    float4 pre[8];
    #pragma unroll
    for (int i = 0; i < 8; i++) {
        int f = tid + i * 256;
        pre[i] = *(const float4*)(kvb + (size_t)(f >> 5) * 128 + ((f & 31) << 2));
    }

    for (int tt = 0; tt < ntile; tt++) {
        const int t0 = tt * 64;
        __syncthreads();                       // prior tile's compute done
        // split + store K/V hi/lo
        #pragma unroll
        for (int i = 0; i < 8; i++) {
            int f = tid + i * 256;
            int r = f >> 5;
            int c4 = (f & 31) << 2;
            float4 h, l;
            h.x = tf32_rna(pre[i].x); l.x = tf32_rna(pre[i].x - h.x);
            h.y = tf32_rna(pre[i].y); l.y = tf32_rna(pre[i].y - h.y);
            h.z = tf32_rna(pre[i].z); l.z = tf32_rna(pre[i].z - h.z);
            h.w = tf32_rna(pre[i].w); l.w = tf32_rna(pre[i].w - h.w);
            if (c4 < 64) {
                *(float4*)&Khi[r * 68 + c4] = h;
                *(float4*)&Klo[r * 68 + c4] = l;
            } else {
                *(float4*)&Vhi[r * 68 + c4 - 64] = h;
                *(float4*)&Vlo[r * 68 + c4 - 64] = l;
            }
        }
        __syncthreads();

        if (tt + 1 < ntile) {                  // prefetch next tile
            const float* kvn = kvb + (size_t)(t0 + 64) * 128;
            #pragma unroll
            for (int i = 0; i < 8; i++) {
                int f = tid + i * 256;
                pre[i] = *(const float4*)(kvn + (size_t)(f >> 5) * 128 + ((f & 31) << 2));
            }
        }

        if (t0 <= s_w) {                       // warp has work in this tile
            // ---- QK^T: scores in C-fragments ----
            float sc[8][4];
            #pragma unroll
            for (int nf = 0; nf < 8; nf++)
                #pragma unroll
                for (int r = 0; r < 4; r++) sc[nf][r] = 0.f;

            #pragma unroll
            for (int kf = 0; kf < 8; kf++) {
                #pragma unroll
                for (int nf = 0; nf < 8; nf++) {
                    const int kb = (nf * 8 + grp) * 68 + kf * 8 + q;
                    uint32_t bh[2], bl[2];
                    bh[0] = __float_as_uint(Khi[kb]);
                    bh[1] = __float_as_uint(Khi[kb + 4]);
                    bl[0] = __float_as_uint(Klo[kb]);
                    bl[1] = __float_as_uint(Klo[kb + 4]);
                    mma8(sc[nf], qh[kf], bh);
                    mma8(sc[nf], qh[kf], bl);
                    mma8(sc[nf], ql[kf], bh);
                }
            }

            // ---- causal mask (warp-uniform, column-only) ----
            if (t0 + 63 > s_w) {
                #pragma unroll
                for (int nf = 0; nf < 8; nf++) {
                    const int t = t0 + nf * 8 + 2 * q;
                    if (t > s_w)     { sc[nf][0] = -1e30f; sc[nf][2] = -1e30f; }
                    if (t + 1 > s_w) { sc[nf][1] = -1e30f; sc[nf][3] = -1e30f; }
                }
            }

            // ---- online softmax (rows grp / grp+8; quad shfl reduce) ----
            float r0 = -1e30f, r1 = -1e30f;
            #pragma unroll
            for (int nf = 0; nf < 8; nf++) {
                r0 = fmaxf(r0, fmaxf(sc[nf][0], sc[nf][1]));
                r1 = fmaxf(r1, fmaxf(sc[nf][2], sc[nf][3]));
            }
            r0 = fmaxf(r0, __shfl_xor_sync(0xffffffffu, r0, 1));
            r0 = fmaxf(r0, __shfl_xor_sync(0xffffffffu, r0, 2));
            r1 = fmaxf(r1, __shfl_xor_sync(0xffffffffu, r1, 1));
            r1 = fmaxf(r1, __shfl_xor_sync(0xffffffffu, r1, 2));
            const float mn0 = fmaxf(m0, r0), mn1 = fmaxf(m1, r1);
            const float c0 = __expf(m0 - mn0), c1 = __expf(m1 - mn1);
            m0 = mn0; m1 = mn1;

            float rs0 = 0.f, rs1 = 0.f;
            #pragma unroll
            for (int nf = 0; nf < 8; nf++) {
                float p0 = __expf(sc[nf][0] - m0);
                float p1 = __expf(sc[nf][1] - m0);
                float p2 = __expf(sc[nf][2] - m1);
                float p3 = __expf(sc[nf][3] - m1);
                rs0 += p0 + p1;
                rs1 += p2 + p3;
                *(float2*)&Pme[grp * 72 + nf * 8 + 2 * q]       = make_float2(p0, p1);
                *(float2*)&Pme[(grp + 8) * 72 + nf * 8 + 2 * q] = make_float2(p2, p3);
            }
            rs0 += __shfl_xor_sync(0xffffffffu, rs0, 1);
            rs0 += __shfl_xor_sync(0xffffffffu, rs0, 2);
            rs1 += __shfl_xor_sync(0xffffffffu, rs1, 1);
            rs1 += __shfl_xor_sync(0xffffffffu, rs1, 2);
            l0 = l0 * c0 + rs0;
            l1 = l1 * c1 + rs1;

            #pragma unroll
            for (int nf = 0; nf < 8; nf++) {
                acc[nf][0] *= c0; acc[nf][1] *= c0;
                acc[nf][2] *= c1; acc[nf][3] *= c1;
            }
            __syncwarp();

            // ---- PV: A = P (split on read), B = V hi/lo ----
            #pragma unroll
            for (int kf = 0; kf < 8; kf++) {
                uint32_t ph[4], pl[4];
                split_tf32(Pme[grp * 72 + kf * 8 + q],            ph[0], pl[0]);
                split_tf32(Pme[(grp + 8) * 72 + kf * 8 + q],      ph[1], pl[1]);
                split_tf32(Pme[grp * 72 + kf * 8 + q + 4],        ph[2], pl[2]);
                split_tf32(Pme[(grp + 8) * 72 + kf * 8 + q + 4],  ph[3], pl[3]);
                #pragma unroll
                for (int nf = 0; nf < 8; nf++) {
                    const int vb0 = (kf * 8 + q) * 68 + nf * 8 + grp;
                    const int vb1 = (kf * 8 + q + 4) * 68 + nf * 8 + grp;
                    uint32_t bh[2], bl[2];
                    bh[0] = __float_as_uint(Vhi[vb0]);
                    bh[1] = __float_as_uint(Vhi[vb1]);
                    bl[0] = __float_as_uint(Vlo[vb0]);
                    bl[1] = __float_as_uint(Vlo[vb1]);
                    mma8(acc[nf], ph, bh);
                    mma8(acc[nf], ph, bl);
                    mma8(acc[nf], pl, bh);
                }
            }
        }
    }

    // ---- normalize + write ----
    const float inv0 = 1.0f / l0, inv1 = 1.0f / l1;
    float* ob = g_attnout + (size_t)(b * CS + s_w) * 1024;
    #pragma unroll
    for (int nf = 0; nf < 8; nf++) {
        *(float2*)&ob[grp * 64 + nf * 8 + 2 * q] =
            make_float2(acc[nf][0] * inv0, acc[nf][1] * inv0);
        *(float2*)&ob[(grp + 8) * 64 + nf * 8 + 2 * q] =
            make_float2(acc[nf][2] * inv1, acc[nf][3] * inv1);
    }
}

// ---------------------------------------------------------------------------
extern "C" void kernel_launch(void* const* d_in, const int* in_sizes, int n_in,
                              void* d_out, int out_size)
{
    const float* x    = (const float*)d_in[0];
    const float* Wqkv = (const float*)d_in[1];
    const float* bqkv = (const float*)d_in[2];
    const float* Wout = (const float*)d_in[3];
    const float* bout = (const float*)d_in[4];
    float* out = (float*)d_out;

    cudaFuncSetAttribute(gemm_mma<0>, cudaFuncAttributeMaxDynamicSharedMemorySize,
                         GEMM_SMEM_BYTES);
    cudaFuncSetAttribute(gemm_mma<1>, cudaFuncAttributeMaxDynamicSharedMemorySize,
                         GEMM_SMEM_BYTES);
    cudaFuncSetAttribute(attn_tc, cudaFuncAttributeMaxDynamicSharedMemorySize,
                         ATTN_SMEM_BYTES);

    // 1) head-sum the K/V weights+biases (linearity of the head reduction)
    prep_k<<<512, 256>>>(Wqkv, bqkv);
    // 2) fused q + kv_sum GEMM on tensor cores (mma.sync tf32, 3xTF32)
    gemm_mma<0><<<dim3(9, 32), 256, GEMM_SMEM_BYTES>>>(x, Wqkv, bqkv, nullptr);
    // 3) causal flash attention on tensor cores (mma.sync tf32, 3xTF32)
    attn_tc<<<dim3(CS / 8, CB), 256, ATTN_SMEM_BYTES>>>();
    // 4) output projection on tensor cores (mma.sync tf32, 3xTF32)
    gemm_mma<1><<<dim3(8, 32), 256, GEMM_SMEM_BYTES>>>(nullptr, Wout, bout, out);
}

// round 13
// speedup vs baseline: 2.6939x; 1.0424x over previous
#include <cuda_runtime.h>
#include <cstdint>

// Problem constants
#define CB 2
#define CS 2048
#define CD 1024
#define CH 16
#define CHD 64
#define CM (CB*CS)   // 4096 tokens

// Scratch (allocation-free rule: __device__ globals)
__device__ float g_q[(size_t)CM * CD];        // 16 MB
__device__ float g_kvh[(size_t)CM * 128];     // hi tf32 of [k_sum | v_sum]
__device__ float g_kvl[(size_t)CM * 128];     // lo tf32 of [k_sum | v_sum]
__device__ float g_attnout[(size_t)CM * CD];  // 16 MB
__device__ float g_Wkv[128 * CD];             // head-summed K/V weights
__device__ float g_bkv[128];

// ---------------------------------------------------------------------------
// helpers
// ---------------------------------------------------------------------------
__device__ __forceinline__ uint32_t smem_u32(const void* p) {
    uint32_t a;
    asm("{ .reg .u64 t; cvta.to.shared.u64 t, %1; cvt.u32.u64 %0, t; }"
        : "=r"(a) : "l"(p));
    return a;
}
__device__ __forceinline__ float tf32_rna(float x) {
    uint32_t r;
    asm("cvt.rna.tf32.f32 %0, %1;" : "=r"(r) : "f"(x));
    return __uint_as_float(r);
}
__device__ __forceinline__ void split_tf32(float x, uint32_t& h, uint32_t& l) {
    float hf = tf32_rna(x);
    h = __float_as_uint(hf);
    l = __float_as_uint(tf32_rna(x - hf));
}
// mma.sync m16n8k8 tf32 (portable path: no sm_103a-only ISA)
__device__ __forceinline__ void mma8(float* c, const uint32_t* a, const uint32_t* b) {
    asm volatile(
        "mma.sync.aligned.m16n8k8.row.col.f32.tf32.tf32.f32 "
        "{%0,%1,%2,%3}, {%4,%5,%6,%7}, {%8,%9}, {%0,%1,%2,%3};"
        : "+f"(c[0]), "+f"(c[1]), "+f"(c[2]), "+f"(c[3])
        : "r"(a[0]), "r"(a[1]), "r"(a[2]), "r"(a[3]), "r"(b[0]), "r"(b[1]));
}
// cp.async (Ampere-baseline; fine on plain sm_103)
__device__ __forceinline__ void cp16(uint32_t dst, const float* src) {
    asm volatile("cp.async.cg.shared.global [%0], [%1], 16;"
                 :: "r"(dst), "l"(src) : "memory");
}
#define CP_COMMIT() asm volatile("cp.async.commit_group;" ::: "memory")
#define CP_WAIT0()  asm volatile("cp.async.wait_group 0;" ::: "memory")

// ---------------------------------------------------------------------------
// Kernel 1: reduce Wqkv over heads -> Wk_sum (rows 0..63), Wv_sum (rows 64..127)
// ---------------------------------------------------------------------------
__global__ __launch_bounds__(256) void prep_k(const float* __restrict__ Wqkv,
                                              const float* __restrict__ bqkv)
{
    int idx = blockIdx.x * 256 + threadIdx.x;
    if (idx < 128 * 1024) {
        int r = idx >> 10;          // 0..127
        int c = idx & 1023;
        int rr = r & 63;
        int base = (r < 64 ? 1024 : 2048) + rr;
        float sum = 0.f;
        #pragma unroll
        for (int h = 0; h < 16; h++)
            sum += Wqkv[(size_t)(base + h * 64) * CD + c];
        g_Wkv[(size_t)r * CD + c] = sum;
    }
    if (idx < 128) {
        int rr = idx & 63;
        int base = (idx < 64 ? 1024 : 2048) + rr;
        float s = 0.f;
        #pragma unroll
        for (int h = 0; h < 16; h++)
            s += bqkv[base + h * 64];
        g_bkv[idx] = s;
    }
}

// ---------------------------------------------------------------------------
// tf32 mma.sync GEMM (3xTF32), double-buffered smem, ONE sync per K-tile.
// Hazard proof (2-stage rotation): stores to buf[kt&1] at iter kt are ordered
// after sync#(kt-1), which all warps pass only after finishing their iter-
// (kt-2) MMA reads of that same buffer. Reads of buf[kt&1] at iter kt are
// ordered after sync#kt, i.e. after all stores. One barrier/iter suffices.
// MODE 0: A=x, N=1152 (cols <1024 -> g_q; cols >=1024 -> g_kvh/g_kvl split)
// MODE 1: A=g_attnout, B=Wout, C=d_out
// ---------------------------------------------------------------------------
#define LDP 36
#define GSTAGE (4 * 128 * LDP)                  // floats per stage
#define GEMM_SMEM_BYTES (2 * GSTAGE * 4)        // 147456

template<int MODE>
__global__ __launch_bounds__(256) void gemm_mma(const float* __restrict__ A,
                                                const float* __restrict__ Bw,
                                                const float* __restrict__ bias,
                                                float* __restrict__ Cout)
{
    extern __shared__ float sm[];

    const int tid = threadIdx.x;
    const int wid = tid >> 5;
    const int lane = tid & 31;
    const int grp = lane >> 2;
    const int q   = lane & 3;
    const int warp_m = wid >> 2;
    const int warp_n = wid & 3;

    const int n0 = blockIdx.x * 128;
    const int m0 = blockIdx.y * 128;

    const float* Ap = (MODE == 0) ? A : g_attnout;
    const float* Bp;
    const float* bp;
    if (MODE == 0 && n0 >= CD) { Bp = g_Wkv; bp = g_bkv; }
    else                       { Bp = Bw + (size_t)n0 * CD; bp = bias + n0; }
    const float* Abase = Ap + (size_t)m0 * CD;

    float acc[4][4][4];
    #pragma unroll
    for (int mt = 0; mt < 4; mt++)
        #pragma unroll
        for (int nt = 0; nt < 4; nt++)
            #pragma unroll
            for (int r = 0; r < 4; r++) acc[mt][nt][r] = 0.f;

    int rowv[4], colv[4];
    #pragma unroll
    for (int i = 0; i < 4; i++) {
        int f = tid + i * 256;
        rowv[i] = f >> 3;
        colv[i] = (f & 7) << 2;
    }

    float4 ra[4], rb[4];
    #pragma unroll
    for (int i = 0; i < 4; i++) {
        ra[i] = *(const float4*)(Abase + (size_t)rowv[i] * CD + colv[i]);
        rb[i] = *(const float4*)(Bp    + (size_t)rowv[i] * CD + colv[i]);
    }

    for (int kt = 0; kt < 32; kt++) {
        float* buf = sm + (kt & 1) * GSTAGE;
        float* Ash = buf;
        float* Asl = buf + 128 * LDP;
        float* Bsh = buf + 2 * 128 * LDP;
        float* Bsl = buf + 3 * 128 * LDP;

        #pragma unroll
        for (int i = 0; i < 4; i++) {
            const int so = rowv[i] * LDP + colv[i];
            float4 h, l;
            h.x = tf32_rna(ra[i].x); l.x = tf32_rna(ra[i].x - h.x);
            h.y = tf32_rna(ra[i].y); l.y = tf32_rna(ra[i].y - h.y);
            h.z = tf32_rna(ra[i].z); l.z = tf32_rna(ra[i].z - h.z);
            h.w = tf32_rna(ra[i].w); l.w = tf32_rna(ra[i].w - h.w);
            *(float4*)&Ash[so] = h;  *(float4*)&Asl[so] = l;
            h.x = tf32_rna(rb[i].x); l.x = tf32_rna(rb[i].x - h.x);
            h.y = tf32_rna(rb[i].y); l.y = tf32_rna(rb[i].y - h.y);
            h.z = tf32_rna(rb[i].z); l.z = tf32_rna(rb[i].z - h.z);
            h.w = tf32_rna(rb[i].w); l.w = tf32_rna(rb[i].w - h.w);
            *(float4*)&Bsh[so] = h;  *(float4*)&Bsl[so] = l;
        }
        __syncthreads();                       // the ONLY barrier per tile

        if (kt < 31) {
            const int k0 = (kt + 1) * 32;
            #pragma unroll
            for (int i = 0; i < 4; i++) {
                ra[i] = *(const float4*)(Abase + (size_t)rowv[i] * CD + k0 + colv[i]);
                rb[i] = *(const float4*)(Bp    + (size_t)rowv[i] * CD + k0 + colv[i]);
            }
        }

        #pragma unroll
        for (int ks = 0; ks < 4; ks++) {
            const int k = ks * 8 + q;
            uint32_t ah[4][4], al[4][4], bh[4][2], bl[4][2];
            #pragma unroll
            for (int mt = 0; mt < 4; mt++) {
                const int mb = (warp_m * 64 + mt * 16 + grp) * LDP;
                ah[mt][0] = __float_as_uint(Ash[mb + k]);
                ah[mt][1] = __float_as_uint(Ash[mb + 8 * LDP + k]);
                ah[mt][2] = __float_as_uint(Ash[mb + k + 4]);
                ah[mt][3] = __float_as_uint(Ash[mb + 8 * LDP + k + 4]);
                al[mt][0] = __float_as_uint(Asl[mb + k]);
                al[mt][1] = __float_as_uint(Asl[mb + 8 * LDP + k]);
                al[mt][2] = __float_as_uint(Asl[mb + k + 4]);
                al[mt][3] = __float_as_uint(Asl[mb + 8 * LDP + k + 4]);
            }
            #pragma unroll
            for (int nt = 0; nt < 4; nt++) {
                const int nb = (warp_n * 32 + nt * 8 + grp) * LDP;
                bh[nt][0] = __float_as_uint(Bsh[nb + k]);
                bh[nt][1] = __float_as_uint(Bsh[nb + k + 4]);
                bl[nt][0] = __float_as_uint(Bsl[nb + k]);
                bl[nt][1] = __float_as_uint(Bsl[nb + k + 4]);
            }
            #pragma unroll
            for (int mt = 0; mt < 4; mt++)
                #pragma unroll
                for (int nt = 0; nt < 4; nt++) {
                    mma8(acc[mt][nt], ah[mt], bh[nt]);
                    mma8(acc[mt][nt], ah[mt], bl[nt]);
                    mma8(acc[mt][nt], al[mt], bh[nt]);
                }
        }
    }

    // epilogue
    #pragma unroll
    for (int mt = 0; mt < 4; mt++) {
        const int m = m0 + warp_m * 64 + mt * 16 + grp;
        #pragma unroll
        for (int nt = 0; nt < 4; nt++) {
            const int nl = warp_n * 32 + nt * 8 + q * 2;
            float2 v0, v1;
            v0.x = acc[mt][nt][0] + bp[nl];
            v0.y = acc[mt][nt][1] + bp[nl + 1];
            v1.x = acc[mt][nt][2] + bp[nl];
            v1.y = acc[mt][nt][3] + bp[nl + 1];
            if (MODE == 0) {
                if (n0 < CD) {
                    *(float2*)&g_q[(size_t)m * CD + n0 + nl] = v0;
                    *(float2*)&g_q[(size_t)(m + 8) * CD + n0 + nl] = v1;
                } else {
                    // pre-split K/V hi/lo here: every attention block reuses it
                    float2 h0, l0f, h1, l1f;
                    h0.x = tf32_rna(v0.x); l0f.x = tf32_rna(v0.x - h0.x);
                    h0.y = tf32_rna(v0.y); l0f.y = tf32_rna(v0.y - h0.y);
                    h1.x = tf32_rna(v1.x); l1f.x = tf32_rna(v1.x - h1.x);
                    h1.y = tf32_rna(v1.y); l1f.y = tf32_rna(v1.y - h1.y);
                    *(float2*)&g_kvh[(size_t)m * 128 + nl] = h0;
                    *(float2*)&g_kvl[(size_t)m * 128 + nl] = l0f;
                    *(float2*)&g_kvh[(size_t)(m + 8) * 128 + nl] = h1;
                    *(float2*)&g_kvl[(size_t)(m + 8) * 128 + nl] = l1f;
                }
            } else {
                *(float2*)&Cout[(size_t)m * CD + n0 + nl] = v0;
                *(float2*)&Cout[(size_t)(m + 8) * CD + n0 + nl] = v1;
            }
        }
    }
}

// ---------------------------------------------------------------------------
// Kernel 3: flash attention on tensor cores. K/V pre-split hi/lo in global;
// tiles streamed via cp.async into double-buffered smem, ONE sync per tile.
// Block = 8 s x 16 heads = 128 rows; warp w owns s = s0+w.
// ---------------------------------------------------------------------------
#define ASTAGE 17408                            // floats: 4 planes x 64 x 68
#define AT_PW  (2 * ASTAGE)                     // 34816
#define ATTN_SMEM_BYTES ((AT_PW + 8 * 16 * 72) * 4)   // 176128

__global__ __launch_bounds__(256) void attn_tc()
{
    extern __shared__ float smf[];
    const uint32_t sb = smem_u32(smf);

    const int b   = blockIdx.y;
    const int s0  = blockIdx.x * 8;
    const int tid = threadIdx.x;
    const int w   = tid >> 5;
    const int lane = tid & 31;
    const int grp = lane >> 2;
    const int q   = lane & 3;
    const int s_w = s0 + w;
    float* Pme = smf + AT_PW + w * (16 * 72);

    const float* kvh = g_kvh + (size_t)(b * CS) * 128;
    const float* kvl = g_kvl + (size_t)(b * CS) * 128;

    // per-thread cp.async roles: 16 x 16B chunks cover 4 planes x 64 x 64
    int pl_[16], r_[16], c_[16];
    #pragma unroll
    for (int i = 0; i < 16; i++) {
        int c = tid + i * 256;        // 0..4095
        pl_[i] = c >> 10;             // plane 0..3: Khi,Klo,Vhi,Vlo
        r_[i]  = (c & 1023) >> 4;     // 0..63
        c_[i]  = (c & 15) << 2;       // 0..60
    }

    // ---- Q A-fragments (scaled, hi/lo split, live all tiles) ----
    uint32_t qh[8][4], ql[8][4];
    {
        const float* qb = g_q + (size_t)(b * CS + s_w) * 1024;
        #pragma unroll
        for (int kf = 0; kf < 8; kf++) {
            float a0 = 0.125f * qb[grp * 64 + kf * 8 + q];
            float a1 = 0.125f * qb[(grp + 8) * 64 + kf * 8 + q];
            float a2 = 0.125f * qb[grp * 64 + kf * 8 + q + 4];
            float a3 = 0.125f * qb[(grp + 8) * 64 + kf * 8 + q + 4];
            split_tf32(a0, qh[kf][0], ql[kf][0]);
            split_tf32(a1, qh[kf][1], ql[kf][1]);
            split_tf32(a2, qh[kf][2], ql[kf][2]);
            split_tf32(a3, qh[kf][3], ql[kf][3]);
        }
    }

    float acc[8][4];
    #pragma unroll
    for (int nf = 0; nf < 8; nf++)
        #pragma unroll
        for (int r = 0; r < 4; r++) acc[nf][r] = 0.f;
    float m0 = -1e30f, m1 = -1e30f, l0 = 0.f, l1 = 0.f;

    const int ntile = ((s0 + 7) >> 6) + 1;

    // issue tile 0 into stage 0
    #pragma unroll
    for (int i = 0; i < 16; i++) {
        const uint32_t dst = sb + (uint32_t)(pl_[i] * 4352 + r_[i] * 68 + c_[i]) * 4;
        const float* src = (pl_[i] & 1 ? kvl : kvh)
                         + (size_t)r_[i] * 128 + ((pl_[i] >> 1) ? 64 : 0) + c_[i];
        cp16(dst, src);
    }
    CP_COMMIT();

    for (int tt = 0; tt < ntile; tt++) {
        const int t0 = tt * 64;
        const float* stage = smf + (tt & 1) * ASTAGE;
        const float* Khi = stage;
        const float* Klo = stage + 4352;
        const float* Vhi = stage + 8704;
        const float* Vlo = stage + 13056;

        CP_WAIT0();
        __syncthreads();                       // single barrier per tile

        if (tt + 1 < ntile) {                  // issue next tile into other stage
            const uint32_t sbase = sb + (uint32_t)(((tt + 1) & 1) * ASTAGE) * 4;
            const size_t gshift = (size_t)(t0 + 64) * 128;
            #pragma unroll
            for (int i = 0; i < 16; i++) {
                const uint32_t dst = sbase + (uint32_t)(pl_[i] * 4352 + r_[i] * 68 + c_[i]) * 4;
                const float* src = (pl_[i] & 1 ? kvl : kvh)
                                 + gshift + (size_t)r_[i] * 128 + ((pl_[i] >> 1) ? 64 : 0) + c_[i];
                cp16(dst, src);
            }
            CP_COMMIT();
        }

        if (t0 <= s_w) {
            // ---- QK^T ----
            float sc[8][4];
            #pragma unroll
            for (int nf = 0; nf < 8; nf++)
                #pragma unroll
                for (int r = 0; r < 4; r++) sc[nf][r] = 0.f;

            #pragma unroll
            for (int kf = 0; kf < 8; kf++) {
                #pragma unroll
                for (int nf = 0; nf < 8; nf++) {
                    const int kb = (nf * 8 + grp) * 68 + kf * 8 + q;
                    uint32_t bh[2], bl[2];
                    bh[0] = __float_as_uint(Khi[kb]);
                    bh[1] = __float_as_uint(Khi[kb + 4]);
                    bl[0] = __float_as_uint(Klo[kb]);
                    bl[1] = __float_as_uint(Klo[kb + 4]);
                    mma8(sc[nf], qh[kf], bh);
                    mma8(sc[nf], qh[kf], bl);
                    mma8(sc[nf], ql[kf], bh);
                }
            }

            // ---- causal mask (warp-uniform, column-only) ----
            if (t0 + 63 > s_w) {
                #pragma unroll
                for (int nf = 0; nf < 8; nf++) {
                    const int t = t0 + nf * 8 + 2 * q;
                    if (t > s_w)     { sc[nf][0] = -1e30f; sc[nf][2] = -1e30f; }
                    if (t + 1 > s_w) { sc[nf][1] = -1e30f; sc[nf][3] = -1e30f; }
                }
            }

            // ---- online softmax ----
            float r0 = -1e30f, r1 = -1e30f;
            #pragma unroll
            for (int nf = 0; nf < 8; nf++) {
                r0 = fmaxf(r0, fmaxf(sc[nf][0], sc[nf][1]));
                r1 = fmaxf(r1, fmaxf(sc[nf][2], sc[nf][3]));
            }
            r0 = fmaxf(r0, __shfl_xor_sync(0xffffffffu, r0, 1));
            r0 = fmaxf(r0, __shfl_xor_sync(0xffffffffu, r0, 2));
            r1 = fmaxf(r1, __shfl_xor_sync(0xffffffffu, r1, 1));
            r1 = fmaxf(r1, __shfl_xor_sync(0xffffffffu, r1, 2));
            const float mn0 = fmaxf(m0, r0), mn1 = fmaxf(m1, r1);
            const float c0 = __expf(m0 - mn0), c1 = __expf(m1 - mn1);
            m0 = mn0; m1 = mn1;

            float rs0 = 0.f, rs1 = 0.f;
            #pragma unroll
            for (int nf = 0; nf < 8; nf++) {
                float p0 = __expf(sc[nf][0] - m0);
                float p1 = __expf(sc[nf][1] - m0);
                float p2 = __expf(sc[nf][2] - m1);
                float p3 = __expf(sc[nf][3] - m1);
                rs0 += p0 + p1;
                rs1 += p2 + p3;
                *(float2*)&Pme[grp * 72 + nf * 8 + 2 * q]       = make_float2(p0, p1);
                *(float2*)&Pme[(grp + 8) * 72 + nf * 8 + 2 * q] = make_float2(p2, p3);
            }
            rs0 += __shfl_xor_sync(0xffffffffu, rs0, 1);
            rs0 += __shfl_xor_sync(0xffffffffu, rs0, 2);
            rs1 += __shfl_xor_sync(0xffffffffu, rs1, 1);
            rs1 += __shfl_xor_sync(0xffffffffu, rs1, 2);
            l0 = l0 * c0 + rs0;
            l1 = l1 * c1 + rs1;

            #pragma unroll
            for (int nf = 0; nf < 8; nf++) {
                acc[nf][0] *= c0; acc[nf][1] *= c0;
                acc[nf][2] *= c1; acc[nf][3] *= c1;
            }
            __syncwarp();

            // ---- PV ----
            #pragma unroll
            for (int kf = 0; kf < 8; kf++) {
                uint32_t ph[4], pl2[4];
                split_tf32(Pme[grp * 72 + kf * 8 + q],            ph[0], pl2[0]);
                split_tf32(Pme[(grp + 8) * 72 + kf * 8 + q],      ph[1], pl2[1]);
                split_tf32(Pme[grp * 72 + kf * 8 + q + 4],        ph[2], pl2[2]);
                split_tf32(Pme[(grp + 8) * 72 + kf * 8 + q + 4],  ph[3], pl2[3]);
                #pragma unroll
                for (int nf = 0; nf < 8; nf++) {
                    const int vb0 = (kf * 8 + q) * 68 + nf * 8 + grp;
                    const int vb1 = (kf * 8 + q + 4) * 68 + nf * 8 + grp;
                    uint32_t bh[2], bl[2];
                    bh[0] = __float_as_uint(Vhi[vb0]);
                    bh[1] = __float_as_uint(Vhi[vb1]);
                    bl[0] = __float_as_uint(Vlo[vb0]);
                    bl[1] = __float_as_uint(Vlo[vb1]);
                    mma8(acc[nf], ph, bh);
                    mma8(acc[nf], ph, bl);
                    mma8(acc[nf], pl2, bh);
                }
            }
        }
    }

    // ---- normalize + write ----
    const float inv0 = 1.0f / l0, inv1 = 1.0f / l1;
    float* ob = g_attnout + (size_t)(b * CS + s_w) * 1024;
    #pragma unroll
    for (int nf = 0; nf < 8; nf++) {
        *(float2*)&ob[grp * 64 + nf * 8 + 2 * q] =
            make_float2(acc[nf][0] * inv0, acc[nf][1] * inv0);
        *(float2*)&ob[(grp + 8) * 64 + nf * 8 + 2 * q] =
            make_float2(acc[nf][2] * inv1, acc[nf][3] * inv1);
    }
}

// ---------------------------------------------------------------------------
extern "C" void kernel_launch(void* const* d_in, const int* in_sizes, int n_in,
                              void* d_out, int out_size)
{
    const float* x    = (const float*)d_in[0];
    const float* Wqkv = (const float*)d_in[1];
    const float* bqkv = (const float*)d_in[2];
    const float* Wout = (const float*)d_in[3];
    const float* bout = (const float*)d_in[4];
    float* out = (float*)d_out;

    cudaFuncSetAttribute(gemm_mma<0>, cudaFuncAttributeMaxDynamicSharedMemorySize,
                         GEMM_SMEM_BYTES);
    cudaFuncSetAttribute(gemm_mma<1>, cudaFuncAttributeMaxDynamicSharedMemorySize,
                         GEMM_SMEM_BYTES);
    cudaFuncSetAttribute(attn_tc, cudaFuncAttributeMaxDynamicSharedMemorySize,
                         ATTN_SMEM_BYTES);

    // 1) head-sum the K/V weights+biases (linearity of the head reduction)
    prep_k<<<512, 256>>>(Wqkv, bqkv);
    // 2) fused q + kv_sum GEMM on tensor cores (kv written pre-split hi/lo)
    gemm_mma<0><<<dim3(9, 32), 256, GEMM_SMEM_BYTES>>>(x, Wqkv, bqkv, nullptr);
    // 3) causal flash attention on tensor cores (cp.async double-buffered K/V)
    attn_tc<<<dim3(CS / 8, CB), 256, ATTN_SMEM_BYTES>>>();
    // 4) output projection on tensor cores
    gemm_mma<1><<<dim3(8, 32), 256, GEMM_SMEM_BYTES>>>(nullptr, Wout, bout, out);
}